// round 1
// baseline (speedup 1.0000x reference)
#include <cuda_runtime.h>
#include <math.h>

// ---------------- static problem config ----------------
#define HD 256          // hidden
#define NN 32768        // total nodes layer 1
#define BGR 64          // graphs
#define NPG 512         // nodes/graph
#define EE 524288       // edges
#define KP1 256         // kept after pool 1
#define KP2 128         // kept after pool 2
#define N2 (BGR*KP1)    // 16384 nodes layer 2
#define LTOK 16
#define PDIM 128

// ---------------- scratch (device globals; no allocation allowed) ----------------
__device__ float g_x[NN*HD];        // 32MB: st output -> layer1 gcn out -> layer2 gcn out
__device__ float g_h[NN*HD];        // 32MB: gemm outputs
__device__ float g_x1[N2*HD];       // 16MB: pool1 output
__device__ float g_x2[BGR*KP2*HD];  // 8MB : pool2 output
__device__ float g_w[EE];
__device__ float g_w1[EE];
__device__ int   g_src1[EE];
__device__ int   g_dst1[EE];
__device__ float g_deg[NN];
__device__ int   g_cnt[NN];
__device__ int   g_off[NN+1];
__device__ int   g_cur[NN];
__device__ int   g_csr_src[EE];
__device__ float g_csr_nrm[EE];
__device__ float g_score[NN];
__device__ float g_gate[NN];
__device__ int   g_permold[N2];
__device__ float g_gatev[N2];
__device__ int   g_noo[NN];
__device__ float g_out[BGR*HD];
__device__ float g_pn[2];

// ---------------- kernels ----------------

// token embed + masked mean. grid=NN, block=256
__global__ void k_st(const int* __restrict__ tok, const float* __restrict__ emb,
                     float* __restrict__ x) {
    int n = blockIdx.x, c = threadIdx.x;
    float acc = 0.f; int cnt = 0;
#pragma unroll
    for (int l = 0; l < LTOK; l++) {
        int t = tok[n*LTOK + l];
        if (t != 0) { acc += emb[(size_t)t*HD + c]; cnt++; }
    }
    x[(size_t)n*HD + c] = acc / fmaxf((float)cnt, 1.f);
}

// C[M,256] = A[M,256] @ B[256,256]. 64x64 tile, 16x16 threads, 4x4/thread.
__global__ void k_gemm(const float* __restrict__ A, const float* __restrict__ Bm,
                       float* __restrict__ C, int M) {
    __shared__ float As[64][16];
    __shared__ float Bs[16][64];
    int tx = threadIdx.x, ty = threadIdx.y;
    int tid = ty*16 + tx;
    int bm = blockIdx.y, bn = blockIdx.x;
    float acc[4][4] = {};
    for (int k0 = 0; k0 < HD; k0 += 16) {
#pragma unroll
        for (int i = 0; i < 4; i++) {
            int idx = tid + i*256;
            int r = idx >> 4, c = idx & 15;
            As[r][c] = A[(size_t)(bm*64 + r)*HD + k0 + c];
        }
#pragma unroll
        for (int i = 0; i < 4; i++) {
            int idx = tid + i*256;
            int r = idx >> 6, c = idx & 63;
            Bs[r][c] = Bm[(size_t)(k0 + r)*HD + bn*64 + c];
        }
        __syncthreads();
#pragma unroll
        for (int kk = 0; kk < 16; kk++) {
            float ra[4], rb[4];
#pragma unroll
            for (int i = 0; i < 4; i++) ra[i] = As[ty*4 + i][kk];
#pragma unroll
            for (int j = 0; j < 4; j++) rb[j] = Bs[kk][tx*4 + j];
#pragma unroll
            for (int i = 0; i < 4; i++)
#pragma unroll
                for (int j = 0; j < 4; j++) acc[i][j] += ra[i]*rb[j];
        }
        __syncthreads();
    }
#pragma unroll
    for (int i = 0; i < 4; i++)
#pragma unroll
        for (int j = 0; j < 4; j++)
            C[(size_t)(bm*64 + ty*4 + i)*HD + bn*64 + tx*4 + j] = acc[i][j];
}

__global__ void k_edgew(const float* __restrict__ ea, float* __restrict__ w, int E) {
    int e = blockIdx.x*blockDim.x + threadIdx.x;
    if (e < E) w[e] = 0.5f*(ea[2*e] + ea[2*e+1]);
}

__global__ void k_initdeg(float* deg, int* cnt, int n) {
    int i = blockIdx.x*blockDim.x + threadIdx.x;
    if (i < n) { deg[i] = 1.f; cnt[i] = 0; }
}

__global__ void k_fill_int(int* a, int v, int n) {
    int i = blockIdx.x*blockDim.x + threadIdx.x;
    if (i < n) a[i] = v;
}

__global__ void k_degcnt(const int* __restrict__ dst, const float* __restrict__ w,
                         float* deg, int* cnt, int E) {
    int e = blockIdx.x*blockDim.x + threadIdx.x;
    if (e >= E) return;
    float we = w[e];
    if (we != 0.f) {
        atomicAdd(&deg[dst[e]], we);
        atomicAdd(&cnt[dst[e]], 1);
    }
}

// single-block exclusive scan of cnt[n] -> off[n+1], cur[n]
__global__ void k_scan(const int* __restrict__ cnt, int* __restrict__ off,
                       int* __restrict__ cur, int n) {
    __shared__ int sh[1024];
    __shared__ int s_carry;
    int tid = threadIdx.x;
    if (tid == 0) s_carry = 0;
    __syncthreads();
    for (int base = 0; base < n; base += 1024) {
        int i = base + tid;
        int v = (i < n) ? cnt[i] : 0;
        sh[tid] = v; __syncthreads();
        for (int d = 1; d < 1024; d <<= 1) {
            int t = (tid >= d) ? sh[tid - d] : 0;
            __syncthreads();
            sh[tid] += t;
            __syncthreads();
        }
        int excl = sh[tid] - v + s_carry;
        if (i < n) { off[i] = excl; cur[i] = excl; }
        __syncthreads();
        if (tid == 1023) s_carry += sh[1023];
        __syncthreads();
    }
    if (tid == 0) off[n] = s_carry;
}

__global__ void k_scatter(const int* __restrict__ src, const int* __restrict__ dst,
                          const float* __restrict__ w, const float* __restrict__ deg,
                          int* cur, int* __restrict__ csr_src,
                          float* __restrict__ csr_nrm, int E) {
    int e = blockIdx.x*blockDim.x + threadIdx.x;
    if (e >= E) return;
    float we = w[e];
    if (we == 0.f) return;
    int s = src[e], d = dst[e];
    int p = atomicAdd(&cur[d], 1);
    csr_src[p] = s;
    csr_nrm[p] = rsqrtf(deg[s]) * we * rsqrtf(deg[d]);
}

// agg + self term + bias + relu. grid=n, block=256
__global__ void k_agg(const float* __restrict__ h, const int* __restrict__ csr_src,
                      const float* __restrict__ csr_nrm, const int* __restrict__ off,
                      const float* __restrict__ deg, const float* __restrict__ bias,
                      float* __restrict__ xout) {
    int v = blockIdx.x, c = threadIdx.x;
    int s0 = off[v], s1 = off[v+1];
    float acc = 0.f;
    for (int k = s0; k < s1; k++) {
        int s = csr_src[k];
        acc += h[(size_t)s*HD + c] * csr_nrm[k];
    }
    float r = acc + h[(size_t)v*HD + c] / deg[v] + bias[c];
    xout[(size_t)v*HD + c] = fmaxf(r, 0.f);
}

__global__ void k_pnorm(const float* __restrict__ p0, const float* __restrict__ p1,
                        float* __restrict__ pn) {
    __shared__ float red[256];
    int tid = threadIdx.x;
    float v0 = p0[tid], v1 = p1[tid];
    red[tid] = v0*v0; __syncthreads();
    for (int s = 128; s > 0; s >>= 1) { if (tid < s) red[tid] += red[tid+s]; __syncthreads(); }
    if (tid == 0) pn[0] = 1.f / sqrtf(red[0]);
    __syncthreads();
    red[tid] = v1*v1; __syncthreads();
    for (int s = 128; s > 0; s >>= 1) { if (tid < s) red[tid] += red[tid+s]; __syncthreads(); }
    if (tid == 0) pn[1] = 1.f / sqrtf(red[0]);
}

// score[node] = dot(x[node], p) * pn[pidx]. grid = n, block = 256
__global__ void k_score(const float* __restrict__ x, const float* __restrict__ p,
                        const float* __restrict__ pn, int pidx, float* __restrict__ score) {
    __shared__ float red[256];
    int v = blockIdx.x, tid = threadIdx.x;
    red[tid] = x[(size_t)v*HD + tid] * p[tid];
    __syncthreads();
    for (int s = 128; s > 0; s >>= 1) { if (tid < s) red[tid] += red[tid+s]; __syncthreads(); }
    if (tid == 0) score[v] = red[0] * pn[pidx];
}

// gate[node] = dot(x[node], wg) + bg. grid = n, block = 256
__global__ void k_gate(const float* __restrict__ x, const float* __restrict__ wg,
                       const float* __restrict__ bg, float* __restrict__ gate) {
    __shared__ float red[256];
    int v = blockIdx.x, tid = threadIdx.x;
    red[tid] = x[(size_t)v*HD + tid] * wg[tid];
    __syncthreads();
    for (int s = 128; s > 0; s >>= 1) { if (tid < s) red[tid] += red[tid+s]; __syncthreads(); }
    if (tid == 0) gate[v] = red[0] + bg[0];
}

// per-graph bitonic top-K (desc score, asc idx tie-break == jax top_k).
// grid = B, block = M threads.
template<int M, int K>
__global__ void k_topk(const float* __restrict__ score, int* __restrict__ permold,
                       float* __restrict__ gatev, int* __restrict__ noo) {
    __shared__ float s[M];
    __shared__ int   id[M];
    int tid = threadIdx.x, g = blockIdx.x;
    s[tid] = score[g*M + tid];
    id[tid] = tid;
    __syncthreads();
    for (int k = 2; k <= M; k <<= 1) {
        for (int j = k >> 1; j > 0; j >>= 1) {
            int ixj = tid ^ j;
            if (ixj > tid) {
                bool desc = ((tid & k) == 0);
                float sa = s[tid], sb = s[ixj];
                int ia = id[tid], ib = id[ixj];
                bool a_first = (sa > sb) || (sa == sb && ia < ib);
                bool swp = desc ? !a_first : a_first;
                if (swp) { s[tid] = sb; s[ixj] = sa; id[tid] = ib; id[ixj] = ia; }
            }
            __syncthreads();
        }
    }
    if (tid < K) {
        int old = g*M + id[tid];
        int ni = g*K + tid;
        permold[ni] = old;
        gatev[ni] = tanhf(s[tid]);
        if (noo) noo[old] = ni;
    }
}

// gather + gate. grid = nrows, block = 256
__global__ void k_gather(const float* __restrict__ x, const int* __restrict__ permold,
                         const float* __restrict__ gatev, float* __restrict__ xnew) {
    int i = blockIdx.x, c = threadIdx.x;
    xnew[(size_t)i*HD + c] = x[(size_t)permold[i]*HD + c] * gatev[i];
}

__global__ void k_remap(const int* __restrict__ src, const int* __restrict__ dst,
                        const float* __restrict__ w, const int* __restrict__ noo,
                        int* __restrict__ src1, int* __restrict__ dst1,
                        float* __restrict__ w1, int E) {
    int e = blockIdx.x*blockDim.x + threadIdx.x;
    if (e >= E) return;
    int ns = noo[src[e]], nd = noo[dst[e]];
    bool keep = (ns >= 0) && (nd >= 0);
    src1[e] = keep ? ns : 0;
    dst1[e] = keep ? nd : 0;
    w1[e]   = keep ? w[e] : 0.f;
}

// softmax-attention pool over K nodes/graph. grid = B, block = 256
template<int K>
__global__ void k_attpool(const float* __restrict__ x, const float* __restrict__ gate,
                          float* __restrict__ out, int accum) {
    __shared__ float a[256];
    __shared__ float red[256];
    int g = blockIdx.x, tid = threadIdx.x;
    float gv = (tid < K) ? gate[g*K + tid] : -1e30f;
    red[tid] = gv; __syncthreads();
    for (int s = 128; s > 0; s >>= 1) { if (tid < s) red[tid] = fmaxf(red[tid], red[tid+s]); __syncthreads(); }
    float m = red[0]; __syncthreads();
    float e = (tid < K) ? expf(gv - m) : 0.f;
    red[tid] = e; __syncthreads();
    for (int s = 128; s > 0; s >>= 1) { if (tid < s) red[tid] += red[tid+s]; __syncthreads(); }
    float sum = red[0]; __syncthreads();
    a[tid] = e / sum;
    __syncthreads();
    float acc = 0.f;
    const float* xb = x + (size_t)g*K*HD;
    for (int j = 0; j < K; j++) acc += a[j] * xb[(size_t)j*HD + tid];
    if (accum) out[g*HD + tid] += acc;
    else       out[g*HD + tid] = acc;
}

// projection head + L2 norm + output write. grid = B, block = 128
__global__ void k_proj(const float* __restrict__ out, const float* __restrict__ Wp1,
                       const float* __restrict__ bp1, const float* __restrict__ Wp2,
                       const float* __restrict__ bp2, float* logits_dst, float* out_dst) {
    __shared__ float o[HD];
    __shared__ float hh[PDIM];
    __shared__ float red[PDIM];
    int g = blockIdx.x, tid = threadIdx.x;
    o[tid] = out[g*HD + tid];
    o[tid + 128] = out[g*HD + 128 + tid];
    __syncthreads();
    float s = bp1[tid];
    for (int i = 0; i < HD; i++) s += o[i] * Wp1[i*PDIM + tid];
    hh[tid] = fmaxf(s, 0.f);
    __syncthreads();
    float t = bp2[tid];
    for (int i = 0; i < PDIM; i++) t += hh[i] * Wp2[i*PDIM + tid];
    red[tid] = t*t; __syncthreads();
    for (int st = 64; st > 0; st >>= 1) { if (tid < st) red[tid] += red[tid+st]; __syncthreads(); }
    float nrm = fmaxf(sqrtf(red[0]), 1e-12f);
    if (logits_dst) logits_dst[g*PDIM + tid] = t / nrm;
    if (out_dst) {
        out_dst[g*HD + tid] = o[tid];
        out_dst[g*HD + 128 + tid] = o[tid + 128];
    }
}

// ---------------- host launch ----------------
extern "C" void kernel_launch(void* const* d_in, const int* in_sizes, int n_in,
                              void* d_out, int out_size) {
    const int*   tokens    = (const int*)d_in[0];
    const int*   src       = (const int*)d_in[1];
    const int*   dst       = (const int*)d_in[2];
    const float* edge_attr = (const float*)d_in[3];
    const float* emb       = (const float*)d_in[4];
    const float* W0        = (const float*)d_in[5];
    const float* b0        = (const float*)d_in[6];
    const float* W1        = (const float*)d_in[7];
    const float* b1        = (const float*)d_in[8];
    const float* p0        = (const float*)d_in[9];
    const float* p1        = (const float*)d_in[10];
    const float* wg        = (const float*)d_in[11];
    const float* bg        = (const float*)d_in[12];
    const float* Wp1       = (const float*)d_in[13];
    const float* bp1       = (const float*)d_in[14];
    const float* Wp2       = (const float*)d_in[15];
    const float* bp2       = (const float*)d_in[16];

    float *x,*h,*x1,*x2,*w,*w1,*deg,*csr_nrm,*score,*gate,*gatev,*outb,*pn;
    int *src1,*dst1,*cnt,*off,*cur,*csr_src,*permold,*noo;
    cudaGetSymbolAddress((void**)&x, g_x);
    cudaGetSymbolAddress((void**)&h, g_h);
    cudaGetSymbolAddress((void**)&x1, g_x1);
    cudaGetSymbolAddress((void**)&x2, g_x2);
    cudaGetSymbolAddress((void**)&w, g_w);
    cudaGetSymbolAddress((void**)&w1, g_w1);
    cudaGetSymbolAddress((void**)&src1, g_src1);
    cudaGetSymbolAddress((void**)&dst1, g_dst1);
    cudaGetSymbolAddress((void**)&deg, g_deg);
    cudaGetSymbolAddress((void**)&cnt, g_cnt);
    cudaGetSymbolAddress((void**)&off, g_off);
    cudaGetSymbolAddress((void**)&cur, g_cur);
    cudaGetSymbolAddress((void**)&csr_src, g_csr_src);
    cudaGetSymbolAddress((void**)&csr_nrm, g_csr_nrm);
    cudaGetSymbolAddress((void**)&score, g_score);
    cudaGetSymbolAddress((void**)&gate, g_gate);
    cudaGetSymbolAddress((void**)&permold, g_permold);
    cudaGetSymbolAddress((void**)&gatev, g_gatev);
    cudaGetSymbolAddress((void**)&noo, g_noo);
    cudaGetSymbolAddress((void**)&outb, g_out);
    cudaGetSymbolAddress((void**)&pn, g_pn);

    dim3 t16(16, 16);

    // constants
    k_pnorm<<<1, 256>>>(p0, p1, pn);
    // ST encode
    k_st<<<NN, 256>>>(tokens, emb, x);
    // h = x @ W0
    k_gemm<<<dim3(4, NN/64), t16>>>(x, W0, h, NN);
    // edge weights, deg, CSR
    k_edgew<<<EE/256, 256>>>(edge_attr, w, EE);
    k_initdeg<<<NN/256, 256>>>(deg, cnt, NN);
    k_degcnt<<<EE/256, 256>>>(dst, w, deg, cnt, EE);
    k_scan<<<1, 1024>>>(cnt, off, cur, NN);
    k_scatter<<<EE/256, 256>>>(src, dst, w, deg, cur, csr_src, csr_nrm, EE);
    // GCN layer 1 (overwrite x)
    k_agg<<<NN, 256>>>(h, csr_src, csr_nrm, off, deg, b0, x);
    // pool 1
    k_score<<<NN, 256>>>(x, p0, pn, 0, score);
    k_fill_int<<<NN/256, 256>>>(noo, -1, NN);
    k_topk<NPG, KP1><<<BGR, NPG>>>(score, permold, gatev, noo);
    k_gather<<<N2, 256>>>(x, permold, gatev, x1);
    k_remap<<<EE/256, 256>>>(src, dst, w, noo, src1, dst1, w1, EE);
    // attpool 1
    k_gate<<<N2, 256>>>(x1, wg, bg, gate);
    k_attpool<KP1><<<BGR, 256>>>(x1, gate, outb, 0);
    // h = x1 @ W1
    k_gemm<<<dim3(4, N2/64), t16>>>(x1, W1, h, N2);
    // GCN layer 2 CSR (skip dropped edges: w1 == 0)
    k_initdeg<<<N2/256, 256>>>(deg, cnt, N2);
    k_degcnt<<<EE/256, 256>>>(dst1, w1, deg, cnt, EE);
    k_scan<<<1, 1024>>>(cnt, off, cur, N2);
    k_scatter<<<EE/256, 256>>>(src1, dst1, w1, deg, cur, csr_src, csr_nrm, EE);
    k_agg<<<N2, 256>>>(h, csr_src, csr_nrm, off, deg, b1, x);
    // pool 2
    k_score<<<N2, 256>>>(x, p1, pn, 1, score);
    k_topk<KP1, KP2><<<BGR, KP1>>>(score, permold, gatev, (int*)nullptr);
    k_gather<<<BGR*KP2, 256>>>(x, permold, gatev, x2);
    // attpool 2 (accumulate)
    k_gate<<<BGR*KP2, 256>>>(x2, wg, bg, gate);
    k_attpool<KP2><<<BGR, 256>>>(x2, gate, outb, 1);

    // projection head + outputs  (tuple = [logits 64x128, out 64x256] flattened)
    float* logits_dst = (float*)d_out;
    float* out_dst = nullptr;
    if (out_size >= BGR*PDIM + BGR*HD) {
        out_dst = (float*)d_out + BGR*PDIM;
    } else if (out_size == BGR*HD) {
        logits_dst = nullptr;
        out_dst = (float*)d_out;
    }
    k_proj<<<BGR, 128>>>(outb, Wp1, bp1, Wp2, bp2, logits_dst, out_dst);
}

// round 3
// speedup vs baseline: 1.0151x; 1.0151x over previous
#include <cuda_runtime.h>
#include <math.h>

// ---------------- static problem config ----------------
#define HD 256
#define NN 32768
#define BGR 64
#define NPG 512
#define EE 524288
#define KP1 256
#define KP2 128
#define N2 (BGR*KP1)
#define LTOK 16
#define PDIM 128

// ---------------- scratch ----------------
__device__ float g_x[NN*HD];
__device__ float g_h[NN*HD];
__device__ float g_x1[N2*HD];
__device__ float g_x2[BGR*KP2*HD];
__device__ float g_w[EE];
__device__ float g_w1[EE];
__device__ int   g_src1[EE];
__device__ int   g_dst1[EE];
__device__ float g_deg[NN];
__device__ int   g_cnt[NN];
__device__ int   g_off[NN+1];
__device__ int   g_cur[NN];
__device__ int   g_csr_src[EE];
__device__ float g_csr_nrm[EE];
__device__ float g_score[NN];
__device__ float g_gate[NN];
__device__ int   g_permold[N2];
__device__ float g_gatev[N2];
__device__ int   g_noo[NN];
__device__ float g_out[BGR*HD];
__device__ float g_pn[2];

// ---------------- kernels ----------------

// token embed + masked mean. grid=NN, block=256
__global__ void k_st(const int* __restrict__ tok, const float* __restrict__ emb,
                     float* __restrict__ x) {
    int n = blockIdx.x, c = threadIdx.x;
    float acc = 0.f; int cnt = 0;
#pragma unroll
    for (int l = 0; l < LTOK; l++) {
        int t = tok[n*LTOK + l];
        if (t != 0) { acc += emb[(size_t)t*HD + c]; cnt++; }
    }
    x[(size_t)n*HD + c] = acc / fmaxf((float)cnt, 1.f);
}

// C[M,256] = A[M,256] @ B[256,256].
// 128x128 tile, BK=16, 256 threads, 8x8 register tile per thread.
#define BM 128
#define BN 128
#define BK 16
#define ASTRIDE 20
__global__ __launch_bounds__(256, 2)
void k_gemm(const float* __restrict__ A, const float* __restrict__ Bm,
            float* __restrict__ C, int M) {
    __shared__ float As[BM][ASTRIDE];   // rows x k (padded)
    __shared__ float Bs[BK][BN];
    int tid = threadIdx.x;
    int tx = tid & 15, ty = tid >> 4;
    int bn = blockIdx.x, bm = blockIdx.y;
    const float* Ab = A + (size_t)bm*BM*HD;
    const float* Bb = Bm + bn*BN;
    float acc[8][8];
#pragma unroll
    for (int i = 0; i < 8; i++)
#pragma unroll
        for (int j = 0; j < 8; j++) acc[i][j] = 0.f;

    for (int k0 = 0; k0 < HD; k0 += BK) {
        // A tile: 128x16 floats = 512 float4; 2 per thread
#pragma unroll
        for (int i = 0; i < 2; i++) {
            int f = tid + i*256;
            int r = f >> 2, c4 = (f & 3) * 4;
            float4 v = *(const float4*)&Ab[(size_t)r*HD + k0 + c4];
            *(float4*)&As[r][c4] = v;
        }
        // B tile: 16x128 floats = 512 float4; 2 per thread
#pragma unroll
        for (int i = 0; i < 2; i++) {
            int f = tid + i*256;
            int r = f >> 5, c4 = (f & 31) * 4;
            *(float4*)&Bs[r][c4] = *(const float4*)&Bb[(size_t)(k0 + r)*HD + c4];
        }
        __syncthreads();
#pragma unroll
        for (int kk = 0; kk < BK; kk++) {
            float ra[8], rb[8];
#pragma unroll
            for (int i = 0; i < 8; i++) ra[i] = As[ty*8 + i][kk];
            *(float4*)rb     = *(const float4*)&Bs[kk][tx*8];
            *(float4*)(rb+4) = *(const float4*)&Bs[kk][tx*8 + 4];
#pragma unroll
            for (int i = 0; i < 8; i++)
#pragma unroll
                for (int j = 0; j < 8; j++) acc[i][j] += ra[i]*rb[j];
        }
        __syncthreads();
    }
#pragma unroll
    for (int i = 0; i < 8; i++) {
        float* Cr = C + (size_t)(bm*BM + ty*8 + i)*HD + bn*BN + tx*8;
        *(float4*)Cr     = *(float4*)&acc[i][0];
        *(float4*)(Cr+4) = *(float4*)&acc[i][4];
    }
}

// edge weights + deg/cnt init + noo fill. grid covers EE.
__global__ void k_setup(const float* __restrict__ ea, float* __restrict__ w,
                        float* __restrict__ deg, int* __restrict__ cnt,
                        int* __restrict__ noo, int E, int n) {
    int e = blockIdx.x*blockDim.x + threadIdx.x;
    if (e < E) w[e] = 0.5f*(ea[2*e] + ea[2*e+1]);
    if (e < n) { deg[e] = 1.f; cnt[e] = 0; noo[e] = -1; }
}

__global__ void k_degcnt(const int* __restrict__ dst, const float* __restrict__ w,
                         float* deg, int* cnt, int E) {
    int e = blockIdx.x*blockDim.x + threadIdx.x;
    if (e >= E) return;
    float we = w[e];
    if (we != 0.f) {
        atomicAdd(&deg[dst[e]], we);
        atomicAdd(&cnt[dst[e]], 1);
    }
}

// single-block chunked exclusive scan. n divisible by 1024.
__global__ void k_scan(const int* __restrict__ cnt, int* __restrict__ off,
                       int* __restrict__ cur, int n) {
    __shared__ int warpsum[32];
    int tid = threadIdx.x;
    int ch = n >> 10;
    int base = tid * ch;
    int s = 0;
    for (int i = 0; i < ch; i++) s += cnt[base + i];
    int lane = tid & 31, wid = tid >> 5;
    int v = s;
#pragma unroll
    for (int d = 1; d < 32; d <<= 1) {
        int t = __shfl_up_sync(~0u, v, d);
        if (lane >= d) v += t;
    }
    if (lane == 31) warpsum[wid] = v;
    __syncthreads();
    if (wid == 0) {
        int w = warpsum[lane];
#pragma unroll
        for (int d = 1; d < 32; d <<= 1) {
            int t = __shfl_up_sync(~0u, w, d);
            if (lane >= d) w += t;
        }
        warpsum[lane] = w;
    }
    __syncthreads();
    int run = v - s + (wid ? warpsum[wid-1] : 0);
    for (int i = 0; i < ch; i++) {
        off[base + i] = run; cur[base + i] = run;
        run += cnt[base + i];
    }
    if (tid == 1023) off[n] = run;
}

__global__ void k_scatter(const int* __restrict__ src, const int* __restrict__ dst,
                          const float* __restrict__ w, const float* __restrict__ deg,
                          int* cur, int* __restrict__ csr_src,
                          float* __restrict__ csr_nrm, int E) {
    int e = blockIdx.x*blockDim.x + threadIdx.x;
    if (e >= E) return;
    float we = w[e];
    if (we == 0.f) return;
    int s = src[e], d = dst[e];
    int p = atomicAdd(&cur[d], 1);
    csr_src[p] = s;
    csr_nrm[p] = rsqrtf(deg[s]) * we * rsqrtf(deg[d]);
}

// agg + self + bias + relu, fused top-k score. grid=n, block=256
__global__ void k_agg_score(const float* __restrict__ h, const int* __restrict__ csr_src,
                            const float* __restrict__ csr_nrm, const int* __restrict__ off,
                            const float* __restrict__ deg, const float* __restrict__ bias,
                            const float* __restrict__ p, const float* __restrict__ pn,
                            int pidx, float* __restrict__ xout, float* __restrict__ score) {
    __shared__ int   ss[256];
    __shared__ float sn[256];
    __shared__ float red[256];
    int v = blockIdx.x, c = threadIdx.x;
    int s0 = off[v], s1 = off[v+1];
    float acc = 0.f;
    for (int base = s0; base < s1; base += 256) {
        int m = min(256, s1 - base);
        if (c < m) { ss[c] = csr_src[base + c]; sn[c] = csr_nrm[base + c]; }
        __syncthreads();
        int k = 0;
        for (; k + 4 <= m; k += 4) {
            float a0 = h[(size_t)ss[k+0]*HD + c];
            float a1 = h[(size_t)ss[k+1]*HD + c];
            float a2 = h[(size_t)ss[k+2]*HD + c];
            float a3 = h[(size_t)ss[k+3]*HD + c];
            acc += a0*sn[k+0] + a1*sn[k+1] + a2*sn[k+2] + a3*sn[k+3];
        }
        for (; k < m; k++) acc += h[(size_t)ss[k]*HD + c] * sn[k];
        __syncthreads();
    }
    float r = acc + h[(size_t)v*HD + c] / deg[v] + bias[c];
    r = fmaxf(r, 0.f);
    xout[(size_t)v*HD + c] = r;
    // fused score = dot(x_row, p) / ||p||
    red[c] = r * p[c];
    __syncthreads();
    for (int s = 128; s > 0; s >>= 1) { if (c < s) red[c] += red[c+s]; __syncthreads(); }
    if (c == 0) score[v] = red[0] * pn[pidx];
}

__global__ void k_pnorm(const float* __restrict__ p0, const float* __restrict__ p1,
                        float* __restrict__ pn) {
    __shared__ float red[256];
    int tid = threadIdx.x;
    float v0 = p0[tid], v1 = p1[tid];
    red[tid] = v0*v0; __syncthreads();
    for (int s = 128; s > 0; s >>= 1) { if (tid < s) red[tid] += red[tid+s]; __syncthreads(); }
    if (tid == 0) pn[0] = 1.f / sqrtf(red[0]);
    __syncthreads();
    red[tid] = v1*v1; __syncthreads();
    for (int s = 128; s > 0; s >>= 1) { if (tid < s) red[tid] += red[tid+s]; __syncthreads(); }
    if (tid == 0) pn[1] = 1.f / sqrtf(red[0]);
}

// per-graph bitonic top-K (desc score, asc idx tie-break == jax top_k).
template<int M, int K>
__global__ void k_topk(const float* __restrict__ score, int* __restrict__ permold,
                       float* __restrict__ gatev, int* __restrict__ noo) {
    __shared__ float s[M];
    __shared__ int   id[M];
    int tid = threadIdx.x, g = blockIdx.x;
    s[tid] = score[g*M + tid];
    id[tid] = tid;
    __syncthreads();
    for (int k = 2; k <= M; k <<= 1) {
        for (int j = k >> 1; j > 0; j >>= 1) {
            int ixj = tid ^ j;
            if (ixj > tid) {
                bool desc = ((tid & k) == 0);
                float sa = s[tid], sb = s[ixj];
                int ia = id[tid], ib = id[ixj];
                bool a_first = (sa > sb) || (sa == sb && ia < ib);
                bool swp = desc ? !a_first : a_first;
                if (swp) { s[tid] = sb; s[ixj] = sa; id[tid] = ib; id[ixj] = ia; }
            }
            __syncthreads();
        }
    }
    if (tid < K) {
        int old = g*M + id[tid];
        int ni = g*K + tid;
        permold[ni] = old;
        gatev[ni] = tanhf(s[tid]);
        if (noo) noo[old] = ni;
    }
}

// gather + gate scalar fused. grid = nrows, block = 256
__global__ void k_gather_gate(const float* __restrict__ x, const int* __restrict__ permold,
                              const float* __restrict__ gatev, const float* __restrict__ wg,
                              const float* __restrict__ bg, float* __restrict__ xnew,
                              float* __restrict__ gate) {
    __shared__ float red[256];
    int i = blockIdx.x, c = threadIdx.x;
    float val = x[(size_t)permold[i]*HD + c] * gatev[i];
    xnew[(size_t)i*HD + c] = val;
    red[c] = val * wg[c];
    __syncthreads();
    for (int s = 128; s > 0; s >>= 1) { if (c < s) red[c] += red[c+s]; __syncthreads(); }
    if (c == 0) gate[i] = red[0] + bg[0];
}

// edge remap + layer-2 deg/cnt init fused
__global__ void k_remap(const int* __restrict__ src, const int* __restrict__ dst,
                        const float* __restrict__ w, const int* __restrict__ noo,
                        int* __restrict__ src1, int* __restrict__ dst1,
                        float* __restrict__ w1, float* __restrict__ deg,
                        int* __restrict__ cnt, int E, int n) {
    int e = blockIdx.x*blockDim.x + threadIdx.x;
    if (e < E) {
        int ns = noo[src[e]], nd = noo[dst[e]];
        bool keep = (ns >= 0) && (nd >= 0);
        src1[e] = keep ? ns : 0;
        dst1[e] = keep ? nd : 0;
        w1[e]   = keep ? w[e] : 0.f;
    }
    if (e < n) { deg[e] = 1.f; cnt[e] = 0; }
}

// softmax-attention pool over K nodes/graph. grid = B, block = 256
template<int K>
__global__ void k_attpool(const float* __restrict__ x, const float* __restrict__ gate,
                          float* __restrict__ out, int accum) {
    __shared__ float a[256];
    __shared__ float red[256];
    int g = blockIdx.x, tid = threadIdx.x;
    float gv = (tid < K) ? gate[g*K + tid] : -1e30f;
    red[tid] = gv; __syncthreads();
    for (int s = 128; s > 0; s >>= 1) { if (tid < s) red[tid] = fmaxf(red[tid], red[tid+s]); __syncthreads(); }
    float m = red[0]; __syncthreads();
    float e = (tid < K) ? expf(gv - m) : 0.f;
    red[tid] = e; __syncthreads();
    for (int s = 128; s > 0; s >>= 1) { if (tid < s) red[tid] += red[tid+s]; __syncthreads(); }
    float sum = red[0]; __syncthreads();
    a[tid] = e / sum;
    __syncthreads();
    float acc = 0.f;
    const float* xb = x + (size_t)g*K*HD;
#pragma unroll 4
    for (int j = 0; j < K; j++) acc += a[j] * xb[(size_t)j*HD + tid];
    if (accum) out[g*HD + tid] += acc;
    else       out[g*HD + tid] = acc;
}

// projection head + L2 norm + output write. grid = B, block = 128
__global__ void k_proj(const float* __restrict__ out, const float* __restrict__ Wp1,
                       const float* __restrict__ bp1, const float* __restrict__ Wp2,
                       const float* __restrict__ bp2, float* logits_dst, float* out_dst) {
    __shared__ float o[HD];
    __shared__ float hh[PDIM];
    __shared__ float red[PDIM];
    int g = blockIdx.x, tid = threadIdx.x;
    o[tid] = out[g*HD + tid];
    o[tid + 128] = out[g*HD + 128 + tid];
    __syncthreads();
    float s = bp1[tid];
    for (int i = 0; i < HD; i++) s += o[i] * Wp1[i*PDIM + tid];
    hh[tid] = fmaxf(s, 0.f);
    __syncthreads();
    float t = bp2[tid];
    for (int i = 0; i < PDIM; i++) t += hh[i] * Wp2[i*PDIM + tid];
    red[tid] = t*t; __syncthreads();
    for (int st = 64; st > 0; st >>= 1) { if (tid < st) red[tid] += red[tid+st]; __syncthreads(); }
    float nrm = fmaxf(sqrtf(red[0]), 1e-12f);
    if (logits_dst) logits_dst[g*PDIM + tid] = t / nrm;
    if (out_dst) {
        out_dst[g*HD + tid] = o[tid];
        out_dst[g*HD + 128 + tid] = o[tid + 128];
    }
}

// ---------------- host launch ----------------
extern "C" void kernel_launch(void* const* d_in, const int* in_sizes, int n_in,
                              void* d_out, int out_size) {
    const int*   tokens    = (const int*)d_in[0];
    const int*   src       = (const int*)d_in[1];
    const int*   dst       = (const int*)d_in[2];
    const float* edge_attr = (const float*)d_in[3];
    const float* emb       = (const float*)d_in[4];
    const float* W0        = (const float*)d_in[5];
    const float* b0        = (const float*)d_in[6];
    const float* W1        = (const float*)d_in[7];
    const float* b1        = (const float*)d_in[8];
    const float* p0        = (const float*)d_in[9];
    const float* p1        = (const float*)d_in[10];
    const float* wg        = (const float*)d_in[11];
    const float* bg        = (const float*)d_in[12];
    const float* Wp1       = (const float*)d_in[13];
    const float* bp1       = (const float*)d_in[14];
    const float* Wp2       = (const float*)d_in[15];
    const float* bp2       = (const float*)d_in[16];

    float *x,*h,*x1,*x2,*w,*w1,*deg,*csr_nrm,*score,*gate,*gatev,*outb,*pn;
    int *src1,*dst1,*cnt,*off,*cur,*csr_src,*permold,*noo;
    cudaGetSymbolAddress((void**)&x, g_x);
    cudaGetSymbolAddress((void**)&h, g_h);
    cudaGetSymbolAddress((void**)&x1, g_x1);
    cudaGetSymbolAddress((void**)&x2, g_x2);
    cudaGetSymbolAddress((void**)&w, g_w);
    cudaGetSymbolAddress((void**)&w1, g_w1);
    cudaGetSymbolAddress((void**)&src1, g_src1);
    cudaGetSymbolAddress((void**)&dst1, g_dst1);
    cudaGetSymbolAddress((void**)&deg, g_deg);
    cudaGetSymbolAddress((void**)&cnt, g_cnt);
    cudaGetSymbolAddress((void**)&off, g_off);
    cudaGetSymbolAddress((void**)&cur, g_cur);
    cudaGetSymbolAddress((void**)&csr_src, g_csr_src);
    cudaGetSymbolAddress((void**)&csr_nrm, g_csr_nrm);
    cudaGetSymbolAddress((void**)&score, g_score);
    cudaGetSymbolAddress((void**)&gate, g_gate);
    cudaGetSymbolAddress((void**)&permold, g_permold);
    cudaGetSymbolAddress((void**)&gatev, g_gatev);
    cudaGetSymbolAddress((void**)&noo, g_noo);
    cudaGetSymbolAddress((void**)&outb, g_out);
    cudaGetSymbolAddress((void**)&pn, g_pn);

    // constants + edge setup (edgew + deg/cnt init + noo fill)
    k_pnorm<<<1, 256>>>(p0, p1, pn);
    k_setup<<<EE/256, 256>>>(edge_attr, w, deg, cnt, noo, EE, NN);
    k_degcnt<<<EE/256, 256>>>(dst, w, deg, cnt, EE);
    k_scan<<<1, 1024>>>(cnt, off, cur, NN);
    k_scatter<<<EE/256, 256>>>(src, dst, w, deg, cur, csr_src, csr_nrm, EE);
    // ST encode + h = x @ W0
    k_st<<<NN, 256>>>(tokens, emb, x);
    k_gemm<<<dim3(2, NN/BM), 256>>>(x, W0, h, NN);
    // GCN layer 1 + fused score(p0)
    k_agg_score<<<NN, 256>>>(h, csr_src, csr_nrm, off, deg, b0, p0, pn, 0, x, score);
    // pool 1
    k_topk<NPG, KP1><<<BGR, NPG>>>(score, permold, gatev, noo);
    k_gather_gate<<<N2, 256>>>(x, permold, gatev, wg, bg, x1, gate);
    k_remap<<<EE/256, 256>>>(src, dst, w, noo, src1, dst1, w1, deg, cnt, EE, N2);
    k_attpool<KP1><<<BGR, 256>>>(x1, gate, outb, 0);
    // h = x1 @ W1
    k_gemm<<<dim3(2, N2/BM), 256>>>(x1, W1, h, N2);
    // GCN layer 2 CSR
    k_degcnt<<<EE/256, 256>>>(dst1, w1, deg, cnt, EE);
    k_scan<<<1, 1024>>>(cnt, off, cur, N2);
    k_scatter<<<EE/256, 256>>>(src1, dst1, w1, deg, cur, csr_src, csr_nrm, EE);
    k_agg_score<<<N2, 256>>>(h, csr_src, csr_nrm, off, deg, b1, p1, pn, 1, x, score);
    // pool 2
    k_topk<KP1, KP2><<<BGR, KP1>>>(score, permold, gatev, (int*)nullptr);
    k_gather_gate<<<BGR*KP2, 256>>>(x, permold, gatev, wg, bg, x2, gate);
    k_attpool<KP2><<<BGR, 256>>>(x2, gate, outb, 1);

    // projection head + outputs
    float* logits_dst = (float*)d_out;
    float* out_dst = nullptr;
    if (out_size >= BGR*PDIM + BGR*HD) {
        out_dst = (float*)d_out + BGR*PDIM;
    } else if (out_size == BGR*HD) {
        logits_dst = nullptr;
        out_dst = (float*)d_out;
    }
    k_proj<<<BGR, 128>>>(outb, Wp1, bp1, Wp2, bp2, logits_dst, out_dst);
}

// round 4
// speedup vs baseline: 1.1936x; 1.1759x over previous
#include <cuda_runtime.h>
#include <math.h>

// ---------------- static problem config ----------------
#define HD 256
#define NN 32768
#define BGR 64
#define NPG 512
#define EE 524288
#define KP1 256
#define KP2 128
#define N2 (BGR*KP1)
#define LTOK 16
#define PDIM 128

// ---------------- scratch ----------------
__device__ float g_x[NN*HD];
__device__ float g_h[NN*HD];
__device__ float g_x1[N2*HD];
__device__ float g_x2[BGR*KP2*HD];
__device__ float g_w[EE];
__device__ float g_w1[EE];
__device__ int   g_src1[EE];
__device__ int   g_dst1[EE];
__device__ float g_deg[NN];
__device__ int   g_cnt[NN];
__device__ int   g_off[NN+1];
__device__ int   g_cur[NN];
__device__ int   g_bsum[64];
__device__ int   g_csr_src[EE];
__device__ float g_csr_nrm[EE];
__device__ float g_score[NN];
__device__ float g_gate[NN];
__device__ int   g_permold[N2];
__device__ float g_gatev[N2];
__device__ int   g_noo[NN];
__device__ float g_out[BGR*HD];
__device__ float g_pn[2];

// ---------------- kernels ----------------

// token embed + masked mean. grid=NN, block=256
__global__ void k_st(const int* __restrict__ tok, const float* __restrict__ emb,
                     float* __restrict__ x) {
    int n = blockIdx.x, c = threadIdx.x;
    float acc = 0.f; int cnt = 0;
#pragma unroll
    for (int l = 0; l < LTOK; l++) {
        int t = tok[n*LTOK + l];
        if (t != 0) { acc += emb[(size_t)t*HD + c]; cnt++; }
    }
    x[(size_t)n*HD + c] = acc / fmaxf((float)cnt, 1.f);
}

// C[M,256] = A[M,256] @ B[256,256].
// 128x128 tile, BK=16, 256 threads, 8x8 register tile.
// A tile stored k-major (As[k][row], stride 140 floats: 16B aligned rows,
// 2-way conflict only on the staging stores) so the inner loop is pure
// LDS.128 x4 + FFMA x64 per kk (94% FMA issue density).
#define BM 128
#define BN 128
#define BK 16
#define ASTR 140
__global__ __launch_bounds__(256, 2)
void k_gemm(const float* __restrict__ A, const float* __restrict__ Bm,
            float* __restrict__ C, int M) {
    __shared__ float As[BK][ASTR];
    __shared__ float Bs[BK][BN];
    int tid = threadIdx.x;
    int tx = tid & 15, ty = tid >> 4;
    int bn = blockIdx.x, bm = blockIdx.y;
    const float* Ab = A + (size_t)bm*BM*HD;
    const float* Bb = Bm + bn*BN;
    float acc[8][8];
#pragma unroll
    for (int i = 0; i < 8; i++)
#pragma unroll
        for (int j = 0; j < 8; j++) acc[i][j] = 0.f;

    for (int k0 = 0; k0 < HD; k0 += BK) {
        // A tile: 128 rows x 16 k (transpose to k-major in smem)
#pragma unroll
        for (int i = 0; i < 2; i++) {
            int f = tid + i*256;
            int r = f >> 2, c4 = (f & 3) * 4;
            float4 v = *(const float4*)&Ab[(size_t)r*HD + k0 + c4];
            As[c4+0][r] = v.x; As[c4+1][r] = v.y;
            As[c4+2][r] = v.z; As[c4+3][r] = v.w;
        }
        // B tile: 16 x 128
#pragma unroll
        for (int i = 0; i < 2; i++) {
            int f = tid + i*256;
            int r = f >> 5, c4 = (f & 31) * 4;
            *(float4*)&Bs[r][c4] = *(const float4*)&Bb[(size_t)(k0 + r)*HD + c4];
        }
        __syncthreads();
#pragma unroll
        for (int kk = 0; kk < BK; kk++) {
            float ra[8], rb[8];
            *(float4*)ra     = *(const float4*)&As[kk][ty*8];
            *(float4*)(ra+4) = *(const float4*)&As[kk][ty*8 + 4];
            *(float4*)rb     = *(const float4*)&Bs[kk][tx*8];
            *(float4*)(rb+4) = *(const float4*)&Bs[kk][tx*8 + 4];
#pragma unroll
            for (int i = 0; i < 8; i++)
#pragma unroll
                for (int j = 0; j < 8; j++) acc[i][j] += ra[i]*rb[j];
        }
        __syncthreads();
    }
#pragma unroll
    for (int i = 0; i < 8; i++) {
        float* Cr = C + (size_t)(bm*BM + ty*8 + i)*HD + bn*BN + tx*8;
        *(float4*)Cr     = *(float4*)&acc[i][0];
        *(float4*)(Cr+4) = *(float4*)&acc[i][4];
    }
}

// edge weights + deg/cnt init + noo fill. grid covers EE.
__global__ void k_setup(const float* __restrict__ ea, float* __restrict__ w,
                        float* __restrict__ deg, int* __restrict__ cnt,
                        int* __restrict__ noo, int E, int n) {
    int e = blockIdx.x*blockDim.x + threadIdx.x;
    if (e < E) w[e] = 0.5f*(ea[2*e] + ea[2*e+1]);
    if (e < n) { deg[e] = 1.f; cnt[e] = 0; noo[e] = -1; }
}

__global__ void k_degcnt(const int* __restrict__ dst, const float* __restrict__ w,
                         float* deg, int* cnt, int E) {
    int e = blockIdx.x*blockDim.x + threadIdx.x;
    if (e >= E) return;
    float we = w[e];
    if (we != 0.f) {
        atomicAdd(&deg[dst[e]], we);
        atomicAdd(&cnt[dst[e]], 1);
    }
}

// ---- parallel 2-pass exclusive scan (coalesced) ----
// pass 1: per-block exclusive scan of 1024 elems + block total
__global__ void k_scan1(const int* __restrict__ cnt, int* __restrict__ off,
                        int* __restrict__ bsum) {
    __shared__ int warpsum[32];
    int tid = threadIdx.x;
    int gid = blockIdx.x*1024 + tid;
    int lane = tid & 31, wid = tid >> 5;
    int v = cnt[gid];
    int s = v;
#pragma unroll
    for (int d = 1; d < 32; d <<= 1) {
        int t = __shfl_up_sync(~0u, s, d);
        if (lane >= d) s += t;
    }
    if (lane == 31) warpsum[wid] = s;
    __syncthreads();
    if (wid == 0) {
        int w = warpsum[lane];
#pragma unroll
        for (int d = 1; d < 32; d <<= 1) {
            int t = __shfl_up_sync(~0u, w, d);
            if (lane >= d) w += t;
        }
        warpsum[lane] = w;
    }
    __syncthreads();
    int excl = s - v + (wid ? warpsum[wid-1] : 0);
    off[gid] = excl;
    if (tid == 1023) bsum[blockIdx.x] = excl + v;
}

// pass 2: add prefix of block sums (<=32 blocks), emit cur and off[n]
__global__ void k_scan2(int* __restrict__ off, int* __restrict__ cur,
                        const int* __restrict__ bsum, int n) {
    __shared__ int sh[33];
    int tid = threadIdx.x;
    if (tid < 32) {
        int nb = gridDim.x;
        int v = (tid < nb) ? bsum[tid] : 0;
#pragma unroll
        for (int d = 1; d < 32; d <<= 1) {
            int t = __shfl_up_sync(~0u, v, d);
            if (tid >= d) v += t;
        }
        sh[tid+1] = v;
        if (tid == 0) sh[0] = 0;
    }
    __syncthreads();
    int add = sh[blockIdx.x];
    int gid = blockIdx.x*1024 + tid;
    int o = off[gid] + add;
    off[gid] = o;
    cur[gid] = o;
    if (gid == n - 1) off[n] = sh[gridDim.x];
}

__global__ void k_scatter(const int* __restrict__ src, const int* __restrict__ dst,
                          const float* __restrict__ w, const float* __restrict__ deg,
                          int* cur, int* __restrict__ csr_src,
                          float* __restrict__ csr_nrm, int E) {
    int e = blockIdx.x*blockDim.x + threadIdx.x;
    if (e >= E) return;
    float we = w[e];
    if (we == 0.f) return;
    int s = src[e], d = dst[e];
    int p = atomicAdd(&cur[d], 1);
    csr_src[p] = s;
    csr_nrm[p] = rsqrtf(deg[s]) * we * rsqrtf(deg[d]);
}

// agg + self + bias + relu, fused top-k score. grid=n, block=256
__global__ void k_agg_score(const float* __restrict__ h, const int* __restrict__ csr_src,
                            const float* __restrict__ csr_nrm, const int* __restrict__ off,
                            const float* __restrict__ deg, const float* __restrict__ bias,
                            const float* __restrict__ p, const float* __restrict__ pn,
                            int pidx, float* __restrict__ xout, float* __restrict__ score) {
    __shared__ int   ss[256];
    __shared__ float sn[256];
    __shared__ float red[256];
    int v = blockIdx.x, c = threadIdx.x;
    int s0 = off[v], s1 = off[v+1];
    float acc = 0.f;
    for (int base = s0; base < s1; base += 256) {
        int m = min(256, s1 - base);
        if (c < m) { ss[c] = csr_src[base + c]; sn[c] = csr_nrm[base + c]; }
        __syncthreads();
        int k = 0;
        for (; k + 4 <= m; k += 4) {
            float a0 = h[(size_t)ss[k+0]*HD + c];
            float a1 = h[(size_t)ss[k+1]*HD + c];
            float a2 = h[(size_t)ss[k+2]*HD + c];
            float a3 = h[(size_t)ss[k+3]*HD + c];
            acc += a0*sn[k+0] + a1*sn[k+1] + a2*sn[k+2] + a3*sn[k+3];
        }
        for (; k < m; k++) acc += h[(size_t)ss[k]*HD + c] * sn[k];
        __syncthreads();
    }
    float r = acc + h[(size_t)v*HD + c] / deg[v] + bias[c];
    r = fmaxf(r, 0.f);
    xout[(size_t)v*HD + c] = r;
    red[c] = r * p[c];
    __syncthreads();
    for (int s = 128; s > 0; s >>= 1) { if (c < s) red[c] += red[c+s]; __syncthreads(); }
    if (c == 0) score[v] = red[0] * pn[pidx];
}

__global__ void k_pnorm(const float* __restrict__ p0, const float* __restrict__ p1,
                        float* __restrict__ pn) {
    __shared__ float red[256];
    int tid = threadIdx.x;
    float v0 = p0[tid], v1 = p1[tid];
    red[tid] = v0*v0; __syncthreads();
    for (int s = 128; s > 0; s >>= 1) { if (tid < s) red[tid] += red[tid+s]; __syncthreads(); }
    if (tid == 0) pn[0] = 1.f / sqrtf(red[0]);
    __syncthreads();
    red[tid] = v1*v1; __syncthreads();
    for (int s = 128; s > 0; s >>= 1) { if (tid < s) red[tid] += red[tid+s]; __syncthreads(); }
    if (tid == 0) pn[1] = 1.f / sqrtf(red[0]);
}

// per-graph bitonic top-K (desc score, asc idx tie-break == jax top_k).
template<int M, int K>
__global__ void k_topk(const float* __restrict__ score, int* __restrict__ permold,
                       float* __restrict__ gatev, int* __restrict__ noo) {
    __shared__ float s[M];
    __shared__ int   id[M];
    int tid = threadIdx.x, g = blockIdx.x;
    s[tid] = score[g*M + tid];
    id[tid] = tid;
    __syncthreads();
    for (int k = 2; k <= M; k <<= 1) {
        for (int j = k >> 1; j > 0; j >>= 1) {
            int ixj = tid ^ j;
            if (ixj > tid) {
                bool desc = ((tid & k) == 0);
                float sa = s[tid], sb = s[ixj];
                int ia = id[tid], ib = id[ixj];
                bool a_first = (sa > sb) || (sa == sb && ia < ib);
                bool swp = desc ? !a_first : a_first;
                if (swp) { s[tid] = sb; s[ixj] = sa; id[tid] = ib; id[ixj] = ia; }
            }
            __syncthreads();
        }
    }
    if (tid < K) {
        int old = g*M + id[tid];
        int ni = g*K + tid;
        permold[ni] = old;
        gatev[ni] = tanhf(s[tid]);
        if (noo) noo[old] = ni;
    }
}

// gather + gate scalar fused. grid = nrows, block = 256
__global__ void k_gather_gate(const float* __restrict__ x, const int* __restrict__ permold,
                              const float* __restrict__ gatev, const float* __restrict__ wg,
                              const float* __restrict__ bg, float* __restrict__ xnew,
                              float* __restrict__ gate) {
    __shared__ float red[256];
    int i = blockIdx.x, c = threadIdx.x;
    float val = x[(size_t)permold[i]*HD + c] * gatev[i];
    xnew[(size_t)i*HD + c] = val;
    red[c] = val * wg[c];
    __syncthreads();
    for (int s = 128; s > 0; s >>= 1) { if (c < s) red[c] += red[c+s]; __syncthreads(); }
    if (c == 0) gate[i] = red[0] + bg[0];
}

// edge remap + layer-2 deg/cnt init fused
__global__ void k_remap(const int* __restrict__ src, const int* __restrict__ dst,
                        const float* __restrict__ w, const int* __restrict__ noo,
                        int* __restrict__ src1, int* __restrict__ dst1,
                        float* __restrict__ w1, float* __restrict__ deg,
                        int* __restrict__ cnt, int E, int n) {
    int e = blockIdx.x*blockDim.x + threadIdx.x;
    if (e < E) {
        int ns = noo[src[e]], nd = noo[dst[e]];
        bool keep = (ns >= 0) && (nd >= 0);
        src1[e] = keep ? ns : 0;
        dst1[e] = keep ? nd : 0;
        w1[e]   = keep ? w[e] : 0.f;
    }
    if (e < n) { deg[e] = 1.f; cnt[e] = 0; }
}

// softmax-attention pool over K nodes/graph. grid = B, block = 256
template<int K>
__global__ void k_attpool(const float* __restrict__ x, const float* __restrict__ gate,
                          float* __restrict__ out, int accum) {
    __shared__ float a[256];
    __shared__ float red[256];
    int g = blockIdx.x, tid = threadIdx.x;
    float gv = (tid < K) ? gate[g*K + tid] : -1e30f;
    red[tid] = gv; __syncthreads();
    for (int s = 128; s > 0; s >>= 1) { if (tid < s) red[tid] = fmaxf(red[tid], red[tid+s]); __syncthreads(); }
    float m = red[0]; __syncthreads();
    float e = (tid < K) ? expf(gv - m) : 0.f;
    red[tid] = e; __syncthreads();
    for (int s = 128; s > 0; s >>= 1) { if (tid < s) red[tid] += red[tid+s]; __syncthreads(); }
    float sum = red[0]; __syncthreads();
    a[tid] = e / sum;
    __syncthreads();
    float acc = 0.f;
    const float* xb = x + (size_t)g*K*HD;
#pragma unroll 4
    for (int j = 0; j < K; j++) acc += a[j] * xb[(size_t)j*HD + tid];
    if (accum) out[g*HD + tid] += acc;
    else       out[g*HD + tid] = acc;
}

// projection head + L2 norm + output write. grid = B, block = 128
__global__ void k_proj(const float* __restrict__ out, const float* __restrict__ Wp1,
                       const float* __restrict__ bp1, const float* __restrict__ Wp2,
                       const float* __restrict__ bp2, float* logits_dst, float* out_dst) {
    __shared__ float o[HD];
    __shared__ float hh[PDIM];
    __shared__ float red[PDIM];
    int g = blockIdx.x, tid = threadIdx.x;
    o[tid] = out[g*HD + tid];
    o[tid + 128] = out[g*HD + 128 + tid];
    __syncthreads();
    float s = bp1[tid];
    for (int i = 0; i < HD; i++) s += o[i] * Wp1[i*PDIM + tid];
    hh[tid] = fmaxf(s, 0.f);
    __syncthreads();
    float t = bp2[tid];
    for (int i = 0; i < PDIM; i++) t += hh[i] * Wp2[i*PDIM + tid];
    red[tid] = t*t; __syncthreads();
    for (int st = 64; st > 0; st >>= 1) { if (tid < st) red[tid] += red[tid+st]; __syncthreads(); }
    float nrm = fmaxf(sqrtf(red[0]), 1e-12f);
    if (logits_dst) logits_dst[g*PDIM + tid] = t / nrm;
    if (out_dst) {
        out_dst[g*HD + tid] = o[tid];
        out_dst[g*HD + 128 + tid] = o[tid + 128];
    }
}

// ---------------- host launch ----------------
extern "C" void kernel_launch(void* const* d_in, const int* in_sizes, int n_in,
                              void* d_out, int out_size) {
    const int*   tokens    = (const int*)d_in[0];
    const int*   src       = (const int*)d_in[1];
    const int*   dst       = (const int*)d_in[2];
    const float* edge_attr = (const float*)d_in[3];
    const float* emb       = (const float*)d_in[4];
    const float* W0        = (const float*)d_in[5];
    const float* b0        = (const float*)d_in[6];
    const float* W1        = (const float*)d_in[7];
    const float* b1        = (const float*)d_in[8];
    const float* p0        = (const float*)d_in[9];
    const float* p1        = (const float*)d_in[10];
    const float* wg        = (const float*)d_in[11];
    const float* bg        = (const float*)d_in[12];
    const float* Wp1       = (const float*)d_in[13];
    const float* bp1       = (const float*)d_in[14];
    const float* Wp2       = (const float*)d_in[15];
    const float* bp2       = (const float*)d_in[16];

    float *x,*h,*x1,*x2,*w,*w1,*deg,*csr_nrm,*score,*gate,*gatev,*outb,*pn;
    int *src1,*dst1,*cnt,*off,*cur,*bsum,*csr_src,*permold,*noo;
    cudaGetSymbolAddress((void**)&x, g_x);
    cudaGetSymbolAddress((void**)&h, g_h);
    cudaGetSymbolAddress((void**)&x1, g_x1);
    cudaGetSymbolAddress((void**)&x2, g_x2);
    cudaGetSymbolAddress((void**)&w, g_w);
    cudaGetSymbolAddress((void**)&w1, g_w1);
    cudaGetSymbolAddress((void**)&src1, g_src1);
    cudaGetSymbolAddress((void**)&dst1, g_dst1);
    cudaGetSymbolAddress((void**)&deg, g_deg);
    cudaGetSymbolAddress((void**)&cnt, g_cnt);
    cudaGetSymbolAddress((void**)&off, g_off);
    cudaGetSymbolAddress((void**)&cur, g_cur);
    cudaGetSymbolAddress((void**)&bsum, g_bsum);
    cudaGetSymbolAddress((void**)&csr_src, g_csr_src);
    cudaGetSymbolAddress((void**)&csr_nrm, g_csr_nrm);
    cudaGetSymbolAddress((void**)&score, g_score);
    cudaGetSymbolAddress((void**)&gate, g_gate);
    cudaGetSymbolAddress((void**)&permold, g_permold);
    cudaGetSymbolAddress((void**)&gatev, g_gatev);
    cudaGetSymbolAddress((void**)&noo, g_noo);
    cudaGetSymbolAddress((void**)&outb, g_out);
    cudaGetSymbolAddress((void**)&pn, g_pn);

    // constants + edge setup
    k_pnorm<<<1, 256>>>(p0, p1, pn);
    k_setup<<<EE/256, 256>>>(edge_attr, w, deg, cnt, noo, EE, NN);
    k_degcnt<<<EE/256, 256>>>(dst, w, deg, cnt, EE);
    k_scan1<<<NN/1024, 1024>>>(cnt, off, bsum);
    k_scan2<<<NN/1024, 1024>>>(off, cur, bsum, NN);
    k_scatter<<<EE/256, 256>>>(src, dst, w, deg, cur, csr_src, csr_nrm, EE);
    // ST encode + h = x @ W0
    k_st<<<NN, 256>>>(tokens, emb, x);
    k_gemm<<<dim3(2, NN/BM), 256>>>(x, W0, h, NN);
    // GCN layer 1 + fused score(p0)
    k_agg_score<<<NN, 256>>>(h, csr_src, csr_nrm, off, deg, b0, p0, pn, 0, x, score);
    // pool 1
    k_topk<NPG, KP1><<<BGR, NPG>>>(score, permold, gatev, noo);
    k_gather_gate<<<N2, 256>>>(x, permold, gatev, wg, bg, x1, gate);
    k_remap<<<EE/256, 256>>>(src, dst, w, noo, src1, dst1, w1, deg, cnt, EE, N2);
    k_attpool<KP1><<<BGR, 256>>>(x1, gate, outb, 0);
    // h = x1 @ W1
    k_gemm<<<dim3(2, N2/BM), 256>>>(x1, W1, h, N2);
    // GCN layer 2 CSR
    k_degcnt<<<EE/256, 256>>>(dst1, w1, deg, cnt, EE);
    k_scan1<<<N2/1024, 1024>>>(cnt, off, bsum);
    k_scan2<<<N2/1024, 1024>>>(off, cur, bsum, N2);
    k_scatter<<<EE/256, 256>>>(src1, dst1, w1, deg, cur, csr_src, csr_nrm, EE);
    k_agg_score<<<N2, 256>>>(h, csr_src, csr_nrm, off, deg, b1, p1, pn, 1, x, score);
    // pool 2
    k_topk<KP1, KP2><<<BGR, KP1>>>(score, permold, gatev, (int*)nullptr);
    k_gather_gate<<<BGR*KP2, 256>>>(x, permold, gatev, wg, bg, x2, gate);
    k_attpool<KP2><<<BGR, 256>>>(x2, gate, outb, 1);

    // projection head + outputs
    float* logits_dst = (float*)d_out;
    float* out_dst = nullptr;
    if (out_size >= BGR*PDIM + BGR*HD) {
        out_dst = (float*)d_out + BGR*PDIM;
    } else if (out_size == BGR*HD) {
        logits_dst = nullptr;
        out_dst = (float*)d_out;
    }
    k_proj<<<BGR, 128>>>(outb, Wp1, bp1, Wp2, bp2, logits_dst, out_dst);
}

// round 9
// speedup vs baseline: 1.4207x; 1.1902x over previous
#include <cuda_runtime.h>
#include <cuda_bf16.h>
#include <math.h>
#include <stdint.h>

// ---------------- static problem config ----------------
#define HD 256
#define NN 32768
#define BGR 64
#define NPG 512
#define EE 524288
#define KP1 256
#define KP2 128
#define N2 (BGR*KP1)
#define LTOK 16
#define PDIM 128

// ---------------- scratch ----------------
__device__ float g_x[NN*HD];
__device__ float g_h[NN*HD];
__device__ float g_x1[N2*HD];
__device__ float g_x2[BGR*KP2*HD];
__device__ __nv_bfloat16 g_xh[NN*HD];
__device__ __nv_bfloat16 g_xl[NN*HD];
__device__ __nv_bfloat16 g_wth[2*HD*HD];
__device__ __nv_bfloat16 g_wtl[2*HD*HD];
__device__ float g_w[EE];
__device__ float g_w1[EE];
__device__ int   g_src1[EE];
__device__ int   g_dst1[EE];
__device__ float g_deg[NN];
__device__ int   g_cnt[NN];
__device__ int   g_off[NN+1];
__device__ int   g_cur[NN];
__device__ int   g_bsum[64];
__device__ int   g_csr_src[EE];
__device__ float g_csr_nrm[EE];
__device__ float g_score[NN];
__device__ float g_gate[NN];
__device__ int   g_permold[N2];
__device__ float g_gatev[N2];
__device__ int   g_noo[NN];
__device__ float g_out[BGR*HD];
__device__ float g_pn[2];

// ---------------- mma helpers (sm_80+ portable; compiles for plain sm_103) ----
__device__ __forceinline__ uint32_t smem_u32(const void* p) {
    uint32_t a;
    asm("{ .reg .u64 t; cvta.to.shared.u64 t, %1; cvt.u32.u64 %0, t; }" : "=r"(a) : "l"(p));
    return a;
}
#define SWZ128(o) ((o) ^ (((o) >> 3) & 0x70))

__device__ __forceinline__ void ldm4(uint32_t* r, uint32_t addr) {
    asm volatile("ldmatrix.sync.aligned.m8n8.x4.shared.b16 {%0,%1,%2,%3}, [%4];"
        : "=r"(r[0]), "=r"(r[1]), "=r"(r[2]), "=r"(r[3]) : "r"(addr));
}
__device__ __forceinline__ void mma16816(float* d, const uint32_t* a, const uint32_t* b) {
    asm volatile("mma.sync.aligned.m16n8k16.row.col.f32.bf16.bf16.f32 "
        "{%0,%1,%2,%3}, {%4,%5,%6,%7}, {%8,%9}, {%0,%1,%2,%3};"
        : "+f"(d[0]), "+f"(d[1]), "+f"(d[2]), "+f"(d[3])
        : "r"(a[0]), "r"(a[1]), "r"(a[2]), "r"(a[3]), "r"(b[0]), "r"(b[1]));
}

// C[M,256] = (Ah+Al)[M,256] @ Wt^T, Wt[N=256][K=256] k-major, 3-term bf16 split.
// CTA: 512 thr (16 warps 4x4), tile 128x128, K chunks of 64 via 64KB smem.
#define TCH 16384                 // one 128x64 bf16 tile
#define TC_SMEM (4*TCH + 1024)
__global__ __launch_bounds__(512)
void k_gemm_mma(const __nv_bfloat16* __restrict__ Ah, const __nv_bfloat16* __restrict__ Al,
                const __nv_bfloat16* __restrict__ Bth, const __nv_bfloat16* __restrict__ Btl,
                float* __restrict__ C) {
    extern __shared__ char dyn[];
    char* base = (char*)((((uintptr_t)dyn) + 1023) & ~(uintptr_t)1023);
    uint32_t sbase = smem_u32(base);
    int tid = threadIdx.x;
    int wid = tid >> 5, lane = tid & 31;
    int wm = wid & 3, wn = wid >> 2;          // 4x4 warp grid
    int bn = blockIdx.x, bm = blockIdx.y;
    int row0 = bm * 128, n0g = bn * 128;

    float acc[2][4][4];
#pragma unroll
    for (int mt = 0; mt < 2; mt++)
#pragma unroll
        for (int nt = 0; nt < 4; nt++)
#pragma unroll
            for (int r = 0; r < 4; r++) acc[mt][nt][r] = 0.f;

    for (int chunk = 0; chunk < 4; chunk++) {
        if (chunk) __syncthreads();
        int col0 = chunk * 64;
        // stage 4 tiles of 128x64 bf16, SW128-swizzled (2 uint4 per thread per tile)
#pragma unroll
        for (int t = 0; t < 2; t++) {
            int f = tid + t * 512;            // 0..1023
            int r = f >> 3, c8 = (f & 7) * 8;
            uint32_t so = SWZ128((uint32_t)(r * 128 + c8 * 2));
            *(uint4*)(base + 0*TCH + so) = *(const uint4*)&Ah [(size_t)(row0 + r)*HD + col0 + c8];
            *(uint4*)(base + 1*TCH + so) = *(const uint4*)&Al [(size_t)(row0 + r)*HD + col0 + c8];
            *(uint4*)(base + 2*TCH + so) = *(const uint4*)&Bth[(size_t)(n0g  + r)*HD + col0 + c8];
            *(uint4*)(base + 3*TCH + so) = *(const uint4*)&Btl[(size_t)(n0g  + r)*HD + col0 + c8];
        }
        __syncthreads();

#pragma unroll
        for (int ks = 0; ks < 4; ks++) {
            int k0 = ks * 16;
            uint32_t a_h[2][4], a_l[2][4], b_h[2][4], b_l[2][4];
            // A fragments: rows = m, cols = k
#pragma unroll
            for (int mt = 0; mt < 2; mt++) {
                int arow = wm*32 + mt*16 + (lane & 7) + (lane & 8);
                int acol = k0 + (((lane >> 4) & 1) << 3);
                uint32_t so = SWZ128((uint32_t)(arow * 128 + acol * 2));
                ldm4(a_h[mt], sbase + 0*TCH + so);
                ldm4(a_l[mt], sbase + 1*TCH + so);
            }
            // B fragments: ldmatrix rows = n, cols = k (k-major Wt)
#pragma unroll
            for (int np = 0; np < 2; np++) {
                int brow = wn*32 + np*16 + (lane & 7) + (((lane >> 4) & 1) << 3);
                int bcol = k0 + (lane & 8);
                uint32_t so = SWZ128((uint32_t)(brow * 128 + bcol * 2));
                ldm4(b_h[np], sbase + 2*TCH + so);
                ldm4(b_l[np], sbase + 3*TCH + so);
            }
#pragma unroll
            for (int mt = 0; mt < 2; mt++)
#pragma unroll
                for (int nt = 0; nt < 4; nt++) {
                    const uint32_t* bh = &b_h[nt >> 1][(nt & 1) * 2];
                    const uint32_t* bl = &b_l[nt >> 1][(nt & 1) * 2];
                    mma16816(acc[mt][nt], a_h[mt], bh);
                    mma16816(acc[mt][nt], a_h[mt], bl);
                    mma16816(acc[mt][nt], a_l[mt], bh);
                }
        }
    }

    // epilogue
    int g = lane >> 2, i2 = (lane & 3) * 2;
#pragma unroll
    for (int mt = 0; mt < 2; mt++)
#pragma unroll
        for (int nt = 0; nt < 4; nt++) {
            int r = row0 + wm*32 + mt*16 + g;
            int c = n0g + wn*32 + nt*8 + i2;
            float2 v0 = {acc[mt][nt][0], acc[mt][nt][1]};
            float2 v1 = {acc[mt][nt][2], acc[mt][nt][3]};
            *(float2*)&C[(size_t)r*HD + c] = v0;
            *(float2*)&C[(size_t)(r+8)*HD + c] = v1;
        }
}

// ---------------- other kernels ----------------

// token embed + masked mean -> bf16 hi/lo. grid=NN, block=256
__global__ void k_st(const int* __restrict__ tok, const float* __restrict__ emb,
                     __nv_bfloat16* __restrict__ xh, __nv_bfloat16* __restrict__ xl) {
    int n = blockIdx.x, c = threadIdx.x;
    float acc = 0.f; int cnt = 0;
#pragma unroll
    for (int l = 0; l < LTOK; l++) {
        int t = tok[n*LTOK + l];
        if (t != 0) { acc += emb[(size_t)t*HD + c]; cnt++; }
    }
    float m = acc / fmaxf((float)cnt, 1.f);
    __nv_bfloat16 hi = __float2bfloat16(m);
    xh[(size_t)n*HD + c] = hi;
    xl[(size_t)n*HD + c] = __float2bfloat16(m - __bfloat162float(hi));
}

// transpose + bf16-split both weight matrices. grid (8,8,2), block (32,32)
__global__ void k_convW(const float* __restrict__ W0, const float* __restrict__ W1,
                        __nv_bfloat16* __restrict__ wth, __nv_bfloat16* __restrict__ wtl) {
    __shared__ float t[32][33];
    const float* W = blockIdx.z ? W1 : W0;
    int k0 = blockIdx.x*32, n0 = blockIdx.y*32;
    t[threadIdx.y][threadIdx.x] = W[(size_t)(k0+threadIdx.y)*HD + n0+threadIdx.x];
    __syncthreads();
    float v = t[threadIdx.x][threadIdx.y];   // = W[k0+tx][n0+ty]
    __nv_bfloat16 hi = __float2bfloat16(v);
    size_t o = (size_t)blockIdx.z*HD*HD + (size_t)(n0+threadIdx.y)*HD + k0+threadIdx.x;
    wth[o] = hi;
    wtl[o] = __float2bfloat16(v - __bfloat162float(hi));
}

// edge weights + deg/cnt init + noo fill
__global__ void k_setup(const float* __restrict__ ea, float* __restrict__ w,
                        float* __restrict__ deg, int* __restrict__ cnt,
                        int* __restrict__ noo, int E, int n) {
    int e = blockIdx.x*blockDim.x + threadIdx.x;
    if (e < E) w[e] = 0.5f*(ea[2*e] + ea[2*e+1]);
    if (e < n) { deg[e] = 1.f; cnt[e] = 0; noo[e] = -1; }
}

__global__ void k_degcnt(const int* __restrict__ dst, const float* __restrict__ w,
                         float* deg, int* cnt, int E) {
    int e = blockIdx.x*blockDim.x + threadIdx.x;
    if (e >= E) return;
    float we = w[e];
    if (we != 0.f) {
        atomicAdd(&deg[dst[e]], we);
        atomicAdd(&cnt[dst[e]], 1);
    }
}

// parallel 2-pass exclusive scan
__global__ void k_scan1(const int* __restrict__ cnt, int* __restrict__ off,
                        int* __restrict__ bsum) {
    __shared__ int warpsum[32];
    int tid = threadIdx.x;
    int gid = blockIdx.x*1024 + tid;
    int lane = tid & 31, wid = tid >> 5;
    int v = cnt[gid];
    int s = v;
#pragma unroll
    for (int d = 1; d < 32; d <<= 1) {
        int t = __shfl_up_sync(~0u, s, d);
        if (lane >= d) s += t;
    }
    if (lane == 31) warpsum[wid] = s;
    __syncthreads();
    if (wid == 0) {
        int w = warpsum[lane];
#pragma unroll
        for (int d = 1; d < 32; d <<= 1) {
            int t = __shfl_up_sync(~0u, w, d);
            if (lane >= d) w += t;
        }
        warpsum[lane] = w;
    }
    __syncthreads();
    int excl = s - v + (wid ? warpsum[wid-1] : 0);
    off[gid] = excl;
    if (tid == 1023) bsum[blockIdx.x] = excl + v;
}

__global__ void k_scan2(int* __restrict__ off, int* __restrict__ cur,
                        const int* __restrict__ bsum, int n) {
    __shared__ int sh[33];
    int tid = threadIdx.x;
    if (tid < 32) {
        int nb = gridDim.x;
        int v = (tid < nb) ? bsum[tid] : 0;
#pragma unroll
        for (int d = 1; d < 32; d <<= 1) {
            int t = __shfl_up_sync(~0u, v, d);
            if (tid >= d) v += t;
        }
        sh[tid+1] = v;
        if (tid == 0) sh[0] = 0;
    }
    __syncthreads();
    int add = sh[blockIdx.x];
    int gid = blockIdx.x*1024 + tid;
    int o = off[gid] + add;
    off[gid] = o;
    cur[gid] = o;
    if (gid == n - 1) off[n] = sh[gridDim.x];
}

__global__ void k_scatter(const int* __restrict__ src, const int* __restrict__ dst,
                          const float* __restrict__ w, const float* __restrict__ deg,
                          int* cur, int* __restrict__ csr_src,
                          float* __restrict__ csr_nrm, int E) {
    int e = blockIdx.x*blockDim.x + threadIdx.x;
    if (e >= E) return;
    float we = w[e];
    if (we == 0.f) return;
    int s = src[e], d = dst[e];
    int p = atomicAdd(&cur[d], 1);
    csr_src[p] = s;
    csr_nrm[p] = rsqrtf(deg[s]) * we * rsqrtf(deg[d]);
}

// agg + self + bias + relu, fused top-k score. grid=n, block=256
__global__ void k_agg_score(const float* __restrict__ h, const int* __restrict__ csr_src,
                            const float* __restrict__ csr_nrm, const int* __restrict__ off,
                            const float* __restrict__ deg, const float* __restrict__ bias,
                            const float* __restrict__ p, const float* __restrict__ pn,
                            int pidx, float* __restrict__ xout, float* __restrict__ score) {
    __shared__ int   ss[256];
    __shared__ float sn[256];
    __shared__ float red[256];
    int v = blockIdx.x, c = threadIdx.x;
    int s0 = off[v], s1 = off[v+1];
    float acc = 0.f;
    for (int base = s0; base < s1; base += 256) {
        int m = min(256, s1 - base);
        if (c < m) { ss[c] = csr_src[base + c]; sn[c] = csr_nrm[base + c]; }
        __syncthreads();
        int k = 0;
        for (; k + 4 <= m; k += 4) {
            float a0 = h[(size_t)ss[k+0]*HD + c];
            float a1 = h[(size_t)ss[k+1]*HD + c];
            float a2 = h[(size_t)ss[k+2]*HD + c];
            float a3 = h[(size_t)ss[k+3]*HD + c];
            acc += a0*sn[k+0] + a1*sn[k+1] + a2*sn[k+2] + a3*sn[k+3];
        }
        for (; k < m; k++) acc += h[(size_t)ss[k]*HD + c] * sn[k];
        __syncthreads();
    }
    float r = acc + h[(size_t)v*HD + c] / deg[v] + bias[c];
    r = fmaxf(r, 0.f);
    xout[(size_t)v*HD + c] = r;
    red[c] = r * p[c];
    __syncthreads();
    for (int s = 128; s > 0; s >>= 1) { if (c < s) red[c] += red[c+s]; __syncthreads(); }
    if (c == 0) score[v] = red[0] * pn[pidx];
}

__global__ void k_pnorm(const float* __restrict__ p0, const float* __restrict__ p1,
                        float* __restrict__ pn) {
    __shared__ float red[256];
    int tid = threadIdx.x;
    float v0 = p0[tid], v1 = p1[tid];
    red[tid] = v0*v0; __syncthreads();
    for (int s = 128; s > 0; s >>= 1) { if (tid < s) red[tid] += red[tid+s]; __syncthreads(); }
    if (tid == 0) pn[0] = 1.f / sqrtf(red[0]);
    __syncthreads();
    red[tid] = v1*v1; __syncthreads();
    for (int s = 128; s > 0; s >>= 1) { if (tid < s) red[tid] += red[tid+s]; __syncthreads(); }
    if (tid == 0) pn[1] = 1.f / sqrtf(red[0]);
}

// per-graph bitonic top-K (desc score, asc idx tie-break == jax top_k)
template<int M, int K>
__global__ void k_topk(const float* __restrict__ score, int* __restrict__ permold,
                       float* __restrict__ gatev, int* __restrict__ noo) {
    __shared__ float s[M];
    __shared__ int   id[M];
    int tid = threadIdx.x, g = blockIdx.x;
    s[tid] = score[g*M + tid];
    id[tid] = tid;
    __syncthreads();
    for (int k = 2; k <= M; k <<= 1) {
        for (int j = k >> 1; j > 0; j >>= 1) {
            int ixj = tid ^ j;
            if (ixj > tid) {
                bool desc = ((tid & k) == 0);
                float sa = s[tid], sb = s[ixj];
                int ia = id[tid], ib = id[ixj];
                bool a_first = (sa > sb) || (sa == sb && ia < ib);
                bool swp = desc ? !a_first : a_first;
                if (swp) { s[tid] = sb; s[ixj] = sa; id[tid] = ib; id[ixj] = ia; }
            }
            __syncthreads();
        }
    }
    if (tid < K) {
        int old = g*M + id[tid];
        int ni = g*K + tid;
        permold[ni] = old;
        gatev[ni] = tanhf(s[tid]);
        if (noo) noo[old] = ni;
    }
}

// gather + gate + optional bf16 split. grid = nrows, block = 256
__global__ void k_gather_gate(const float* __restrict__ x, const int* __restrict__ permold,
                              const float* __restrict__ gatev, const float* __restrict__ wg,
                              const float* __restrict__ bg, float* __restrict__ xnew,
                              __nv_bfloat16* __restrict__ xh, __nv_bfloat16* __restrict__ xl,
                              float* __restrict__ gate) {
    __shared__ float red[256];
    int i = blockIdx.x, c = threadIdx.x;
    float val = x[(size_t)permold[i]*HD + c] * gatev[i];
    xnew[(size_t)i*HD + c] = val;
    if (xh) {
        __nv_bfloat16 hi = __float2bfloat16(val);
        xh[(size_t)i*HD + c] = hi;
        xl[(size_t)i*HD + c] = __float2bfloat16(val - __bfloat162float(hi));
    }
    red[c] = val * wg[c];
    __syncthreads();
    for (int s = 128; s > 0; s >>= 1) { if (c < s) red[c] += red[c+s]; __syncthreads(); }
    if (c == 0) gate[i] = red[0] + bg[0];
}

// edge remap + layer-2 deg/cnt init fused
__global__ void k_remap(const int* __restrict__ src, const int* __restrict__ dst,
                        const float* __restrict__ w, const int* __restrict__ noo,
                        int* __restrict__ src1, int* __restrict__ dst1,
                        float* __restrict__ w1, float* __restrict__ deg,
                        int* __restrict__ cnt, int E, int n) {
    int e = blockIdx.x*blockDim.x + threadIdx.x;
    if (e < E) {
        int ns = noo[src[e]], nd = noo[dst[e]];
        bool keep = (ns >= 0) && (nd >= 0);
        src1[e] = keep ? ns : 0;
        dst1[e] = keep ? nd : 0;
        w1[e]   = keep ? w[e] : 0.f;
    }
    if (e < n) { deg[e] = 1.f; cnt[e] = 0; }
}

// softmax-attention pool. grid = B, block = 256
template<int K>
__global__ void k_attpool(const float* __restrict__ x, const float* __restrict__ gate,
                          float* __restrict__ out, int accum) {
    __shared__ float a[256];
    __shared__ float red[256];
    int g = blockIdx.x, tid = threadIdx.x;
    float gv = (tid < K) ? gate[g*K + tid] : -1e30f;
    red[tid] = gv; __syncthreads();
    for (int s = 128; s > 0; s >>= 1) { if (tid < s) red[tid] = fmaxf(red[tid], red[tid+s]); __syncthreads(); }
    float m = red[0]; __syncthreads();
    float e = (tid < K) ? expf(gv - m) : 0.f;
    red[tid] = e; __syncthreads();
    for (int s = 128; s > 0; s >>= 1) { if (tid < s) red[tid] += red[tid+s]; __syncthreads(); }
    float sum = red[0]; __syncthreads();
    a[tid] = e / sum;
    __syncthreads();
    float acc = 0.f;
    const float* xb = x + (size_t)g*K*HD;
#pragma unroll 4
    for (int j = 0; j < K; j++) acc += a[j] * xb[(size_t)j*HD + tid];
    if (accum) out[g*HD + tid] += acc;
    else       out[g*HD + tid] = acc;
}

// projection head + L2 norm + output write. grid = B, block = 128
__global__ void k_proj(const float* __restrict__ out, const float* __restrict__ Wp1,
                       const float* __restrict__ bp1, const float* __restrict__ Wp2,
                       const float* __restrict__ bp2, float* logits_dst, float* out_dst) {
    __shared__ float o[HD];
    __shared__ float hh[PDIM];
    __shared__ float red[PDIM];
    int g = blockIdx.x, tid = threadIdx.x;
    o[tid] = out[g*HD + tid];
    o[tid + 128] = out[g*HD + 128 + tid];
    __syncthreads();
    float s = bp1[tid];
    for (int i = 0; i < HD; i++) s += o[i] * Wp1[i*PDIM + tid];
    hh[tid] = fmaxf(s, 0.f);
    __syncthreads();
    float t = bp2[tid];
    for (int i = 0; i < PDIM; i++) t += hh[i] * Wp2[i*PDIM + tid];
    red[tid] = t*t; __syncthreads();
    for (int st = 64; st > 0; st >>= 1) { if (tid < st) red[tid] += red[tid+st]; __syncthreads(); }
    float nrm = fmaxf(sqrtf(red[0]), 1e-12f);
    if (logits_dst) logits_dst[g*PDIM + tid] = t / nrm;
    if (out_dst) {
        out_dst[g*HD + tid] = o[tid];
        out_dst[g*HD + 128 + tid] = o[tid + 128];
    }
}

// ---------------- host launch ----------------
extern "C" void kernel_launch(void* const* d_in, const int* in_sizes, int n_in,
                              void* d_out, int out_size) {
    const int*   tokens    = (const int*)d_in[0];
    const int*   src       = (const int*)d_in[1];
    const int*   dst       = (const int*)d_in[2];
    const float* edge_attr = (const float*)d_in[3];
    const float* emb       = (const float*)d_in[4];
    const float* W0        = (const float*)d_in[5];
    const float* b0        = (const float*)d_in[6];
    const float* W1        = (const float*)d_in[7];
    const float* b1        = (const float*)d_in[8];
    const float* p0        = (const float*)d_in[9];
    const float* p1        = (const float*)d_in[10];
    const float* wg        = (const float*)d_in[11];
    const float* bg        = (const float*)d_in[12];
    const float* Wp1       = (const float*)d_in[13];
    const float* bp1       = (const float*)d_in[14];
    const float* Wp2       = (const float*)d_in[15];
    const float* bp2       = (const float*)d_in[16];

    float *x,*h,*x1,*x2,*w,*w1,*deg,*csr_nrm,*score,*gate,*gatev,*outb,*pn;
    __nv_bfloat16 *xh,*xl,*wth,*wtl;
    int *src1,*dst1,*cnt,*off,*cur,*bsum,*csr_src,*permold,*noo;
    cudaGetSymbolAddress((void**)&x, g_x);
    cudaGetSymbolAddress((void**)&h, g_h);
    cudaGetSymbolAddress((void**)&x1, g_x1);
    cudaGetSymbolAddress((void**)&x2, g_x2);
    cudaGetSymbolAddress((void**)&xh, g_xh);
    cudaGetSymbolAddress((void**)&xl, g_xl);
    cudaGetSymbolAddress((void**)&wth, g_wth);
    cudaGetSymbolAddress((void**)&wtl, g_wtl);
    cudaGetSymbolAddress((void**)&w, g_w);
    cudaGetSymbolAddress((void**)&w1, g_w1);
    cudaGetSymbolAddress((void**)&src1, g_src1);
    cudaGetSymbolAddress((void**)&dst1, g_dst1);
    cudaGetSymbolAddress((void**)&deg, g_deg);
    cudaGetSymbolAddress((void**)&cnt, g_cnt);
    cudaGetSymbolAddress((void**)&off, g_off);
    cudaGetSymbolAddress((void**)&cur, g_cur);
    cudaGetSymbolAddress((void**)&bsum, g_bsum);
    cudaGetSymbolAddress((void**)&csr_src, g_csr_src);
    cudaGetSymbolAddress((void**)&csr_nrm, g_csr_nrm);
    cudaGetSymbolAddress((void**)&score, g_score);
    cudaGetSymbolAddress((void**)&gate, g_gate);
    cudaGetSymbolAddress((void**)&permold, g_permold);
    cudaGetSymbolAddress((void**)&gatev, g_gatev);
    cudaGetSymbolAddress((void**)&noo, g_noo);
    cudaGetSymbolAddress((void**)&outb, g_out);
    cudaGetSymbolAddress((void**)&pn, g_pn);

    static int smem_set = 0;
    if (!smem_set) {
        cudaFuncSetAttribute(k_gemm_mma, cudaFuncAttributeMaxDynamicSharedMemorySize, TC_SMEM);
        smem_set = 1;
    }

    // constants + weight conversion + edge setup
    k_pnorm<<<1, 256>>>(p0, p1, pn);
    k_convW<<<dim3(8,8,2), dim3(32,32)>>>(W0, W1, wth, wtl);
    k_setup<<<EE/256, 256>>>(edge_attr, w, deg, cnt, noo, EE, NN);
    k_degcnt<<<EE/256, 256>>>(dst, w, deg, cnt, EE);
    k_scan1<<<NN/1024, 1024>>>(cnt, off, bsum);
    k_scan2<<<NN/1024, 1024>>>(off, cur, bsum, NN);
    k_scatter<<<EE/256, 256>>>(src, dst, w, deg, cur, csr_src, csr_nrm, EE);
    // ST encode (bf16 split) + h = x @ W0 on tensor cores (mma.sync)
    k_st<<<NN, 256>>>(tokens, emb, xh, xl);
    k_gemm_mma<<<dim3(2, NN/128), 512, TC_SMEM>>>(xh, xl, wth, wtl, h);
    // GCN layer 1 + fused score(p0)
    k_agg_score<<<NN, 256>>>(h, csr_src, csr_nrm, off, deg, b0, p0, pn, 0, x, score);
    // pool 1
    k_topk<NPG, KP1><<<BGR, NPG>>>(score, permold, gatev, noo);
    k_gather_gate<<<N2, 256>>>(x, permold, gatev, wg, bg, x1, xh, xl, gate);
    k_remap<<<EE/256, 256>>>(src, dst, w, noo, src1, dst1, w1, deg, cnt, EE, N2);
    k_attpool<KP1><<<BGR, 256>>>(x1, gate, outb, 0);
    // h = x1 @ W1 on tensor cores
    k_gemm_mma<<<dim3(2, N2/128), 512, TC_SMEM>>>(xh, xl, wth + HD*HD, wtl + HD*HD, h);
    // GCN layer 2 CSR
    k_degcnt<<<EE/256, 256>>>(dst1, w1, deg, cnt, EE);
    k_scan1<<<N2/1024, 1024>>>(cnt, off, bsum);
    k_scan2<<<N2/1024, 1024>>>(off, cur, bsum, N2);
    k_scatter<<<EE/256, 256>>>(src1, dst1, w1, deg, cur, csr_src, csr_nrm, EE);
    k_agg_score<<<N2, 256>>>(h, csr_src, csr_nrm, off, deg, b1, p1, pn, 1, x, score);
    // pool 2
    k_topk<KP1, KP2><<<BGR, KP1>>>(score, permold, gatev, (int*)nullptr);
    k_gather_gate<<<BGR*KP2, 256>>>(x, permold, gatev, wg, bg, x2,
                                    (__nv_bfloat16*)nullptr, (__nv_bfloat16*)nullptr, gate);
    k_attpool<KP2><<<BGR, 256>>>(x2, gate, outb, 1);

    // projection head + outputs
    float* logits_dst = (float*)d_out;
    float* out_dst = nullptr;
    if (out_size >= BGR*PDIM + BGR*HD) {
        out_dst = (float*)d_out + BGR*PDIM;
    } else if (out_size == BGR*HD) {
        logits_dst = nullptr;
        out_dst = (float*)d_out;
    }
    k_proj<<<BGR, 128>>>(outb, Wp1, bp1, Wp2, bp2, logits_dst, out_dst);
}

// round 13
// speedup vs baseline: 1.5187x; 1.0690x over previous
#include <cuda_runtime.h>
#include <cuda_bf16.h>
#include <math.h>
#include <stdint.h>

// ---------------- static problem config ----------------
#define HD 256
#define NN 32768
#define BGR 64
#define NPG 512
#define EE 524288
#define KP1 256
#define KP2 128
#define N2 (BGR*KP1)
#define LTOK 16
#define PDIM 128

// ---------------- scratch ----------------
__device__ float g_x[NN*HD];
__device__ float g_h[NN*HD];
__device__ float g_x1[N2*HD];
__device__ float g_x2[BGR*KP2*HD];
__device__ __nv_bfloat16 g_xh[NN*HD];
__device__ __nv_bfloat16 g_xl[NN*HD];
__device__ __nv_bfloat16 g_wth[2*HD*HD];
__device__ __nv_bfloat16 g_wtl[2*HD*HD];
__device__ float g_w[EE];
__device__ float g_w1[EE];
__device__ int   g_src1[EE];
__device__ int   g_dst1[EE];
__device__ float g_deg[NN];
__device__ int   g_cnt[NN];
__device__ int   g_off[NN+1];
__device__ int   g_cur[NN];
__device__ int   g_bsum[64];
__device__ int   g_csr_src[EE];
__device__ float g_csr_nrm[EE];
__device__ float g_score[NN];
__device__ float g_gate[NN];
__device__ int   g_permold[N2];
__device__ float g_gatev[N2];
__device__ int   g_noo[NN];
__device__ float g_out[BGR*HD];
__device__ float g_pn[2];

// ---------------- mma helpers (sm_80+ portable; compiles for plain sm_103) ----
__device__ __forceinline__ uint32_t smem_u32(const void* p) {
    uint32_t a;
    asm("{ .reg .u64 t; cvta.to.shared.u64 t, %1; cvt.u32.u64 %0, t; }" : "=r"(a) : "l"(p));
    return a;
}
#define SWZ128(o) ((o) ^ (((o) >> 3) & 0x70))

__device__ __forceinline__ void ldm4(uint32_t* r, uint32_t addr) {
    asm volatile("ldmatrix.sync.aligned.m8n8.x4.shared.b16 {%0,%1,%2,%3}, [%4];"
        : "=r"(r[0]), "=r"(r[1]), "=r"(r[2]), "=r"(r[3]) : "r"(addr));
}
__device__ __forceinline__ void mma16816(float* d, const uint32_t* a, const uint32_t* b) {
    asm volatile("mma.sync.aligned.m16n8k16.row.col.f32.bf16.bf16.f32 "
        "{%0,%1,%2,%3}, {%4,%5,%6,%7}, {%8,%9}, {%0,%1,%2,%3};"
        : "+f"(d[0]), "+f"(d[1]), "+f"(d[2]), "+f"(d[3])
        : "r"(a[0]), "r"(a[1]), "r"(a[2]), "r"(a[3]), "r"(b[0]), "r"(b[1]));
}

// C[M,256] = (Ah+Al)[M,256] @ Wt^T, Wt[N=256][K=256] k-major, 3-term bf16 split.
// CTA: 512 thr (16 warps 4x4), tile 128x128, K chunks of 64 via 64KB smem.
#define TCH 16384                 // one 128x64 bf16 tile
#define TC_SMEM (4*TCH + 1024)
__global__ __launch_bounds__(512)
void k_gemm_mma(const __nv_bfloat16* __restrict__ Ah, const __nv_bfloat16* __restrict__ Al,
                const __nv_bfloat16* __restrict__ Bth, const __nv_bfloat16* __restrict__ Btl,
                float* __restrict__ C) {
    extern __shared__ char dyn[];
    char* base = (char*)((((uintptr_t)dyn) + 1023) & ~(uintptr_t)1023);
    uint32_t sbase = smem_u32(base);
    int tid = threadIdx.x;
    int wid = tid >> 5, lane = tid & 31;
    int wm = wid & 3, wn = wid >> 2;          // 4x4 warp grid
    int bn = blockIdx.x, bm = blockIdx.y;
    int row0 = bm * 128, n0g = bn * 128;

    float acc[2][4][4];
#pragma unroll
    for (int mt = 0; mt < 2; mt++)
#pragma unroll
        for (int nt = 0; nt < 4; nt++)
#pragma unroll
            for (int r = 0; r < 4; r++) acc[mt][nt][r] = 0.f;

    for (int chunk = 0; chunk < 4; chunk++) {
        if (chunk) __syncthreads();
        int col0 = chunk * 64;
#pragma unroll
        for (int t = 0; t < 2; t++) {
            int f = tid + t * 512;            // 0..1023
            int r = f >> 3, c8 = (f & 7) * 8;
            uint32_t so = SWZ128((uint32_t)(r * 128 + c8 * 2));
            *(uint4*)(base + 0*TCH + so) = *(const uint4*)&Ah [(size_t)(row0 + r)*HD + col0 + c8];
            *(uint4*)(base + 1*TCH + so) = *(const uint4*)&Al [(size_t)(row0 + r)*HD + col0 + c8];
            *(uint4*)(base + 2*TCH + so) = *(const uint4*)&Bth[(size_t)(n0g  + r)*HD + col0 + c8];
            *(uint4*)(base + 3*TCH + so) = *(const uint4*)&Btl[(size_t)(n0g  + r)*HD + col0 + c8];
        }
        __syncthreads();

#pragma unroll
        for (int ks = 0; ks < 4; ks++) {
            int k0 = ks * 16;
            uint32_t a_h[2][4], a_l[2][4], b_h[2][4], b_l[2][4];
#pragma unroll
            for (int mt = 0; mt < 2; mt++) {
                int arow = wm*32 + mt*16 + (lane & 7) + (lane & 8);
                int acol = k0 + (((lane >> 4) & 1) << 3);
                uint32_t so = SWZ128((uint32_t)(arow * 128 + acol * 2));
                ldm4(a_h[mt], sbase + 0*TCH + so);
                ldm4(a_l[mt], sbase + 1*TCH + so);
            }
#pragma unroll
            for (int np = 0; np < 2; np++) {
                int brow = wn*32 + np*16 + (lane & 7) + (((lane >> 4) & 1) << 3);
                int bcol = k0 + (lane & 8);
                uint32_t so = SWZ128((uint32_t)(brow * 128 + bcol * 2));
                ldm4(b_h[np], sbase + 2*TCH + so);
                ldm4(b_l[np], sbase + 3*TCH + so);
            }
#pragma unroll
            for (int mt = 0; mt < 2; mt++)
#pragma unroll
                for (int nt = 0; nt < 4; nt++) {
                    const uint32_t* bh = &b_h[nt >> 1][(nt & 1) * 2];
                    const uint32_t* bl = &b_l[nt >> 1][(nt & 1) * 2];
                    mma16816(acc[mt][nt], a_h[mt], bh);
                    mma16816(acc[mt][nt], a_h[mt], bl);
                    mma16816(acc[mt][nt], a_l[mt], bh);
                }
        }
    }

    int g = lane >> 2, i2 = (lane & 3) * 2;
#pragma unroll
    for (int mt = 0; mt < 2; mt++)
#pragma unroll
        for (int nt = 0; nt < 4; nt++) {
            int r = row0 + wm*32 + mt*16 + g;
            int c = n0g + wn*32 + nt*8 + i2;
            float2 v0 = {acc[mt][nt][0], acc[mt][nt][1]};
            float2 v1 = {acc[mt][nt][2], acc[mt][nt][3]};
            *(float2*)&C[(size_t)r*HD + c] = v0;
            *(float2*)&C[(size_t)(r+8)*HD + c] = v1;
        }
}

// ---------------- other kernels ----------------

// token embed + masked mean -> bf16 hi/lo. grid=NN, block=256
__global__ void k_st(const int* __restrict__ tok, const float* __restrict__ emb,
                     __nv_bfloat16* __restrict__ xh, __nv_bfloat16* __restrict__ xl) {
    int n = blockIdx.x, c = threadIdx.x;
    float acc = 0.f; int cnt = 0;
#pragma unroll
    for (int l = 0; l < LTOK; l++) {
        int t = tok[n*LTOK + l];
        if (t != 0) { acc += emb[(size_t)t*HD + c]; cnt++; }
    }
    float m = acc / fmaxf((float)cnt, 1.f);
    __nv_bfloat16 hi = __float2bfloat16(m);
    xh[(size_t)n*HD + c] = hi;
    xl[(size_t)n*HD + c] = __float2bfloat16(m - __bfloat162float(hi));
}

// transpose + bf16-split both weight matrices. grid (8,8,2), block (32,32)
__global__ void k_convW(const float* __restrict__ W0, const float* __restrict__ W1,
                        __nv_bfloat16* __restrict__ wth, __nv_bfloat16* __restrict__ wtl) {
    __shared__ float t[32][33];
    const float* W = blockIdx.z ? W1 : W0;
    int k0 = blockIdx.x*32, n0 = blockIdx.y*32;
    t[threadIdx.y][threadIdx.x] = W[(size_t)(k0+threadIdx.y)*HD + n0+threadIdx.x];
    __syncthreads();
    float v = t[threadIdx.x][threadIdx.y];   // = W[k0+tx][n0+ty]
    __nv_bfloat16 hi = __float2bfloat16(v);
    size_t o = (size_t)blockIdx.z*HD*HD + (size_t)(n0+threadIdx.y)*HD + k0+threadIdx.x;
    wth[o] = hi;
    wtl[o] = __float2bfloat16(v - __bfloat162float(hi));
}

// edge weights + deg/cnt init + noo fill
__global__ void k_setup(const float* __restrict__ ea, float* __restrict__ w,
                        float* __restrict__ deg, int* __restrict__ cnt,
                        int* __restrict__ noo, int E, int n) {
    int e = blockIdx.x*blockDim.x + threadIdx.x;
    if (e < E) w[e] = 0.5f*(ea[2*e] + ea[2*e+1]);
    if (e < n) { deg[e] = 1.f; cnt[e] = 0; noo[e] = -1; }
}

__global__ void k_degcnt(const int* __restrict__ dst, const float* __restrict__ w,
                         float* deg, int* cnt, int E) {
    int e = blockIdx.x*blockDim.x + threadIdx.x;
    if (e >= E) return;
    float we = w[e];
    if (we != 0.f) {
        atomicAdd(&deg[dst[e]], we);
        atomicAdd(&cnt[dst[e]], 1);
    }
}

// parallel 2-pass exclusive scan
__global__ void k_scan1(const int* __restrict__ cnt, int* __restrict__ off,
                        int* __restrict__ bsum) {
    __shared__ int warpsum[32];
    int tid = threadIdx.x;
    int gid = blockIdx.x*1024 + tid;
    int lane = tid & 31, wid = tid >> 5;
    int v = cnt[gid];
    int s = v;
#pragma unroll
    for (int d = 1; d < 32; d <<= 1) {
        int t = __shfl_up_sync(~0u, s, d);
        if (lane >= d) s += t;
    }
    if (lane == 31) warpsum[wid] = s;
    __syncthreads();
    if (wid == 0) {
        int w = warpsum[lane];
#pragma unroll
        for (int d = 1; d < 32; d <<= 1) {
            int t = __shfl_up_sync(~0u, w, d);
            if (lane >= d) w += t;
        }
        warpsum[lane] = w;
    }
    __syncthreads();
    int excl = s - v + (wid ? warpsum[wid-1] : 0);
    off[gid] = excl;
    if (tid == 1023) bsum[blockIdx.x] = excl + v;
}

__global__ void k_scan2(int* __restrict__ off, int* __restrict__ cur,
                        const int* __restrict__ bsum, int n) {
    __shared__ int sh[33];
    int tid = threadIdx.x;
    if (tid < 32) {
        int nb = gridDim.x;
        int v = (tid < nb) ? bsum[tid] : 0;
#pragma unroll
        for (int d = 1; d < 32; d <<= 1) {
            int t = __shfl_up_sync(~0u, v, d);
            if (tid >= d) v += t;
        }
        sh[tid+1] = v;
        if (tid == 0) sh[0] = 0;
    }
    __syncthreads();
    int add = sh[blockIdx.x];
    int gid = blockIdx.x*1024 + tid;
    int o = off[gid] + add;
    off[gid] = o;
    cur[gid] = o;
    if (gid == n - 1) off[n] = sh[gridDim.x];
}

__global__ void k_scatter(const int* __restrict__ src, const int* __restrict__ dst,
                          const float* __restrict__ w, const float* __restrict__ deg,
                          int* cur, int* __restrict__ csr_src,
                          float* __restrict__ csr_nrm, int E) {
    int e = blockIdx.x*blockDim.x + threadIdx.x;
    if (e >= E) return;
    float we = w[e];
    if (we == 0.f) return;
    int s = src[e], d = dst[e];
    int p = atomicAdd(&cur[d], 1);
    csr_src[p] = s;
    csr_nrm[p] = rsqrtf(deg[s]) * we * rsqrtf(deg[d]);
}

// agg + self + bias + relu, fused top-k score. grid=n, block=256
__global__ void k_agg_score(const float* __restrict__ h, const int* __restrict__ csr_src,
                            const float* __restrict__ csr_nrm, const int* __restrict__ off,
                            const float* __restrict__ deg, const float* __restrict__ bias,
                            const float* __restrict__ p, const float* __restrict__ pn,
                            int pidx, float* __restrict__ xout, float* __restrict__ score) {
    __shared__ int   ss[256];
    __shared__ float sn[256];
    __shared__ float red[256];
    int v = blockIdx.x, c = threadIdx.x;
    int s0 = off[v], s1 = off[v+1];
    float acc = 0.f;
    for (int base = s0; base < s1; base += 256) {
        int m = min(256, s1 - base);
        if (c < m) { ss[c] = csr_src[base + c]; sn[c] = csr_nrm[base + c]; }
        __syncthreads();
        int k = 0;
        for (; k + 4 <= m; k += 4) {
            float a0 = h[(size_t)ss[k+0]*HD + c];
            float a1 = h[(size_t)ss[k+1]*HD + c];
            float a2 = h[(size_t)ss[k+2]*HD + c];
            float a3 = h[(size_t)ss[k+3]*HD + c];
            acc += a0*sn[k+0] + a1*sn[k+1] + a2*sn[k+2] + a3*sn[k+3];
        }
        for (; k < m; k++) acc += h[(size_t)ss[k]*HD + c] * sn[k];
        __syncthreads();
    }
    float r = acc + h[(size_t)v*HD + c] / deg[v] + bias[c];
    r = fmaxf(r, 0.f);
    xout[(size_t)v*HD + c] = r;
    red[c] = r * p[c];
    __syncthreads();
    for (int s = 128; s > 0; s >>= 1) { if (c < s) red[c] += red[c+s]; __syncthreads(); }
    if (c == 0) score[v] = red[0] * pn[pidx];
}

__global__ void k_pnorm(const float* __restrict__ p0, const float* __restrict__ p1,
                        float* __restrict__ pn) {
    __shared__ float red[256];
    int tid = threadIdx.x;
    float v0 = p0[tid], v1 = p1[tid];
    red[tid] = v0*v0; __syncthreads();
    for (int s = 128; s > 0; s >>= 1) { if (tid < s) red[tid] += red[tid+s]; __syncthreads(); }
    if (tid == 0) pn[0] = 1.f / sqrtf(red[0]);
    __syncthreads();
    red[tid] = v1*v1; __syncthreads();
    for (int s = 128; s > 0; s >>= 1) { if (tid < s) red[tid] += red[tid+s]; __syncthreads(); }
    if (tid == 0) pn[1] = 1.f / sqrtf(red[0]);
}

// per-graph bitonic top-K (desc score, asc idx tie-break == jax top_k)
template<int M, int K>
__global__ void k_topk(const float* __restrict__ score, int* __restrict__ permold,
                       float* __restrict__ gatev, int* __restrict__ noo) {
    __shared__ float s[M];
    __shared__ int   id[M];
    int tid = threadIdx.x, g = blockIdx.x;
    s[tid] = score[g*M + tid];
    id[tid] = tid;
    __syncthreads();
    for (int k = 2; k <= M; k <<= 1) {
        for (int j = k >> 1; j > 0; j >>= 1) {
            int ixj = tid ^ j;
            if (ixj > tid) {
                bool desc = ((tid & k) == 0);
                float sa = s[tid], sb = s[ixj];
                int ia = id[tid], ib = id[ixj];
                bool a_first = (sa > sb) || (sa == sb && ia < ib);
                bool swp = desc ? !a_first : a_first;
                if (swp) { s[tid] = sb; s[ixj] = sa; id[tid] = ib; id[ixj] = ia; }
            }
            __syncthreads();
        }
    }
    if (tid < K) {
        int old = g*M + id[tid];
        int ni = g*K + tid;
        permold[ni] = old;
        gatev[ni] = tanhf(s[tid]);
        if (noo) noo[old] = ni;
    }
}

// gather + gate + optional bf16 split. grid = nrows, block = 256
__global__ void k_gather_gate(const float* __restrict__ x, const int* __restrict__ permold,
                              const float* __restrict__ gatev, const float* __restrict__ wg,
                              const float* __restrict__ bg, float* __restrict__ xnew,
                              __nv_bfloat16* __restrict__ xh, __nv_bfloat16* __restrict__ xl,
                              float* __restrict__ gate) {
    __shared__ float red[256];
    int i = blockIdx.x, c = threadIdx.x;
    float val = x[(size_t)permold[i]*HD + c] * gatev[i];
    xnew[(size_t)i*HD + c] = val;
    if (xh) {
        __nv_bfloat16 hi = __float2bfloat16(val);
        xh[(size_t)i*HD + c] = hi;
        xl[(size_t)i*HD + c] = __float2bfloat16(val - __bfloat162float(hi));
    }
    red[c] = val * wg[c];
    __syncthreads();
    for (int s = 128; s > 0; s >>= 1) { if (c < s) red[c] += red[c+s]; __syncthreads(); }
    if (c == 0) gate[i] = red[0] + bg[0];
}

// edge remap + layer-2 deg/cnt init fused
__global__ void k_remap(const int* __restrict__ src, const int* __restrict__ dst,
                        const float* __restrict__ w, const int* __restrict__ noo,
                        int* __restrict__ src1, int* __restrict__ dst1,
                        float* __restrict__ w1, float* __restrict__ deg,
                        int* __restrict__ cnt, int E, int n) {
    int e = blockIdx.x*blockDim.x + threadIdx.x;
    if (e < E) {
        int ns = noo[src[e]], nd = noo[dst[e]];
        bool keep = (ns >= 0) && (nd >= 0);
        src1[e] = keep ? ns : 0;
        dst1[e] = keep ? nd : 0;
        w1[e]   = keep ? w[e] : 0.f;
    }
    if (e < n) { deg[e] = 1.f; cnt[e] = 0; }
}

// softmax-attention pool. grid = B, block = 256
template<int K>
__global__ void k_attpool(const float* __restrict__ x, const float* __restrict__ gate,
                          float* __restrict__ out, int accum) {
    __shared__ float a[256];
    __shared__ float red[256];
    int g = blockIdx.x, tid = threadIdx.x;
    float gv = (tid < K) ? gate[g*K + tid] : -1e30f;
    red[tid] = gv; __syncthreads();
    for (int s = 128; s > 0; s >>= 1) { if (tid < s) red[tid] = fmaxf(red[tid], red[tid+s]); __syncthreads(); }
    float m = red[0]; __syncthreads();
    float e = (tid < K) ? expf(gv - m) : 0.f;
    red[tid] = e; __syncthreads();
    for (int s = 128; s > 0; s >>= 1) { if (tid < s) red[tid] += red[tid+s]; __syncthreads(); }
    float sum = red[0]; __syncthreads();
    a[tid] = e / sum;
    __syncthreads();
    float acc = 0.f;
    const float* xb = x + (size_t)g*K*HD;
#pragma unroll 4
    for (int j = 0; j < K; j++) acc += a[j] * xb[(size_t)j*HD + tid];
    if (accum) out[g*HD + tid] += acc;
    else       out[g*HD + tid] = acc;
}

// projection head + L2 norm + output write. grid = B, block = 128
__global__ void k_proj(const float* __restrict__ out, const float* __restrict__ Wp1,
                       const float* __restrict__ bp1, const float* __restrict__ Wp2,
                       const float* __restrict__ bp2, float* logits_dst, float* out_dst) {
    __shared__ float o[HD];
    __shared__ float hh[PDIM];
    __shared__ float red[PDIM];
    int g = blockIdx.x, tid = threadIdx.x;
    o[tid] = out[g*HD + tid];
    o[tid + 128] = out[g*HD + 128 + tid];
    __syncthreads();
    float s = bp1[tid];
    for (int i = 0; i < HD; i++) s += o[i] * Wp1[i*PDIM + tid];
    hh[tid] = fmaxf(s, 0.f);
    __syncthreads();
    float t = bp2[tid];
    for (int i = 0; i < PDIM; i++) t += hh[i] * Wp2[i*PDIM + tid];
    red[tid] = t*t; __syncthreads();
    for (int st = 64; st > 0; st >>= 1) { if (tid < st) red[tid] += red[tid+st]; __syncthreads(); }
    float nrm = fmaxf(sqrtf(red[0]), 1e-12f);
    if (logits_dst) logits_dst[g*PDIM + tid] = t / nrm;
    if (out_dst) {
        out_dst[g*HD + tid] = o[tid];
        out_dst[g*HD + 128 + tid] = o[tid + 128];
    }
}

// ---------------- host launch ----------------
extern "C" void kernel_launch(void* const* d_in, const int* in_sizes, int n_in,
                              void* d_out, int out_size) {
    const int*   tokens    = (const int*)d_in[0];
    const int*   src       = (const int*)d_in[1];
    const int*   dst       = (const int*)d_in[2];
    const float* edge_attr = (const float*)d_in[3];
    const float* emb       = (const float*)d_in[4];
    const float* W0        = (const float*)d_in[5];
    const float* b0        = (const float*)d_in[6];
    const float* W1        = (const float*)d_in[7];
    const float* b1        = (const float*)d_in[8];
    const float* p0        = (const float*)d_in[9];
    const float* p1        = (const float*)d_in[10];
    const float* wg        = (const float*)d_in[11];
    const float* bg        = (const float*)d_in[12];
    const float* Wp1       = (const float*)d_in[13];
    const float* bp1       = (const float*)d_in[14];
    const float* Wp2       = (const float*)d_in[15];
    const float* bp2       = (const float*)d_in[16];

    float *x,*h,*x1,*x2,*w,*w1,*deg,*csr_nrm,*score,*gate,*gatev,*outb,*pn;
    __nv_bfloat16 *xh,*xl,*wth,*wtl;
    int *src1,*dst1,*cnt,*off,*cur,*bsum,*csr_src,*permold,*noo;
    cudaGetSymbolAddress((void**)&x, g_x);
    cudaGetSymbolAddress((void**)&h, g_h);
    cudaGetSymbolAddress((void**)&x1, g_x1);
    cudaGetSymbolAddress((void**)&x2, g_x2);
    cudaGetSymbolAddress((void**)&xh, g_xh);
    cudaGetSymbolAddress((void**)&xl, g_xl);
    cudaGetSymbolAddress((void**)&wth, g_wth);
    cudaGetSymbolAddress((void**)&wtl, g_wtl);
    cudaGetSymbolAddress((void**)&w, g_w);
    cudaGetSymbolAddress((void**)&w1, g_w1);
    cudaGetSymbolAddress((void**)&src1, g_src1);
    cudaGetSymbolAddress((void**)&dst1, g_dst1);
    cudaGetSymbolAddress((void**)&deg, g_deg);
    cudaGetSymbolAddress((void**)&cnt, g_cnt);
    cudaGetSymbolAddress((void**)&off, g_off);
    cudaGetSymbolAddress((void**)&cur, g_cur);
    cudaGetSymbolAddress((void**)&bsum, g_bsum);
    cudaGetSymbolAddress((void**)&csr_src, g_csr_src);
    cudaGetSymbolAddress((void**)&csr_nrm, g_csr_nrm);
    cudaGetSymbolAddress((void**)&score, g_score);
    cudaGetSymbolAddress((void**)&gate, g_gate);
    cudaGetSymbolAddress((void**)&permold, g_permold);
    cudaGetSymbolAddress((void**)&gatev, g_gatev);
    cudaGetSymbolAddress((void**)&noo, g_noo);
    cudaGetSymbolAddress((void**)&outb, g_out);
    cudaGetSymbolAddress((void**)&pn, g_pn);

    static cudaStream_t sB;
    static cudaEvent_t e0, eW, eCSR, eT1, eCSR2;
    static int inited = 0;
    if (!inited) {
        cudaFuncSetAttribute(k_gemm_mma, cudaFuncAttributeMaxDynamicSharedMemorySize, TC_SMEM);
        cudaStreamCreateWithFlags(&sB, cudaStreamNonBlocking);
        cudaEventCreateWithFlags(&e0,    cudaEventDisableTiming);
        cudaEventCreateWithFlags(&eW,    cudaEventDisableTiming);
        cudaEventCreateWithFlags(&eCSR,  cudaEventDisableTiming);
        cudaEventCreateWithFlags(&eT1,   cudaEventDisableTiming);
        cudaEventCreateWithFlags(&eCSR2, cudaEventDisableTiming);
        inited = 1;
    }

    // fork aux stream from the (captured) default stream
    cudaEventRecord(e0, 0);
    cudaStreamWaitEvent(sB, e0, 0);

    // ---- aux stream: weight conversion + edge/CSR chain (layer 1) ----
    k_convW<<<dim3(8,8,2), dim3(32,32), 0, sB>>>(W0, W1, wth, wtl);
    cudaEventRecord(eW, sB);
    k_setup<<<EE/256, 256, 0, sB>>>(edge_attr, w, deg, cnt, noo, EE, NN);
    k_degcnt<<<EE/256, 256, 0, sB>>>(dst, w, deg, cnt, EE);
    k_scan1<<<NN/1024, 1024, 0, sB>>>(cnt, off, bsum);
    k_scan2<<<NN/1024, 1024, 0, sB>>>(off, cur, bsum, NN);
    k_scatter<<<EE/256, 256, 0, sB>>>(src, dst, w, deg, cur, csr_src, csr_nrm, EE);
    cudaEventRecord(eCSR, sB);

    // ---- main stream: token chain ----
    k_pnorm<<<1, 256>>>(p0, p1, pn);
    k_st<<<NN, 256>>>(tokens, emb, xh, xl);
    cudaStreamWaitEvent(0, eW, 0);
    k_gemm_mma<<<dim3(2, NN/128), 512, TC_SMEM>>>(xh, xl, wth, wtl, h);
    cudaStreamWaitEvent(0, eCSR, 0);
    k_agg_score<<<NN, 256>>>(h, csr_src, csr_nrm, off, deg, b0, p0, pn, 0, x, score);
    k_topk<NPG, KP1><<<BGR, NPG>>>(score, permold, gatev, noo);
    cudaEventRecord(eT1, 0);

    // ---- aux stream: layer-2 CSR rebuild (needs noo from topk1) ----
    cudaStreamWaitEvent(sB, eT1, 0);
    k_remap<<<EE/256, 256, 0, sB>>>(src, dst, w, noo, src1, dst1, w1, deg, cnt, EE, N2);
    k_degcnt<<<EE/256, 256, 0, sB>>>(dst1, w1, deg, cnt, EE);
    k_scan1<<<N2/1024, 1024, 0, sB>>>(cnt, off, bsum);
    k_scan2<<<N2/1024, 1024, 0, sB>>>(off, cur, bsum, N2);
    k_scatter<<<EE/256, 256, 0, sB>>>(src1, dst1, w1, deg, cur, csr_src, csr_nrm, EE);
    cudaEventRecord(eCSR2, sB);

    // ---- main stream: pool 1 node path + gemm2 (overlaps CSR rebuild) ----
    k_gather_gate<<<N2, 256>>>(x, permold, gatev, wg, bg, x1, xh, xl, gate);
    k_attpool<KP1><<<BGR, 256>>>(x1, gate, outb, 0);
    k_gemm_mma<<<dim3(2, N2/128), 512, TC_SMEM>>>(xh, xl, wth + HD*HD, wtl + HD*HD, h);
    cudaStreamWaitEvent(0, eCSR2, 0);   // join aux stream
    k_agg_score<<<N2, 256>>>(h, csr_src, csr_nrm, off, deg, b1, p1, pn, 1, x, score);
    // pool 2
    k_topk<KP1, KP2><<<BGR, KP1>>>(score, permold, gatev, (int*)nullptr);
    k_gather_gate<<<BGR*KP2, 256>>>(x, permold, gatev, wg, bg, x2,
                                    (__nv_bfloat16*)nullptr, (__nv_bfloat16*)nullptr, gate);
    k_attpool<KP2><<<BGR, 256>>>(x2, gate, outb, 1);

    // projection head + outputs
    float* logits_dst = (float*)d_out;
    float* out_dst = nullptr;
    if (out_size >= BGR*PDIM + BGR*HD) {
        out_dst = (float*)d_out + BGR*PDIM;
    } else if (out_size == BGR*HD) {
        logits_dst = nullptr;
        out_dst = (float*)d_out;
    }
    k_proj<<<BGR, 128>>>(outb, Wp1, bp1, Wp2, bp2, logits_dst, out_dst);
}

// round 16
// speedup vs baseline: 1.6392x; 1.0794x over previous
#include <cuda_runtime.h>
#include <cuda_bf16.h>
#include <math.h>
#include <stdint.h>

// ---------------- static problem config ----------------
#define HD 256
#define NN 32768
#define BGR 64
#define NPG 512
#define EE 524288
#define KP1 256
#define KP2 128
#define N2 (BGR*KP1)
#define LTOK 16
#define PDIM 128

// ---------------- scratch ----------------
__device__ float g_x[NN*HD];
__device__ float g_h[NN*HD];
__device__ float g_x1[N2*HD];
__device__ __nv_bfloat16 g_xh[NN*HD];
__device__ __nv_bfloat16 g_xl[NN*HD];
__device__ __nv_bfloat16 g_wth[2*HD*HD];
__device__ __nv_bfloat16 g_wtl[2*HD*HD];
__device__ float g_w[EE];
__device__ float g_w1[EE];
__device__ int   g_src1[EE];
__device__ int   g_dst1[EE];
__device__ float g_deg[NN];
__device__ int   g_cnt[NN];
__device__ int   g_off[NN+1];
__device__ int   g_cur[NN];
__device__ int   g_bsum[64];
__device__ int   g_csr_src[EE];
__device__ float g_csr_nrm[EE];
__device__ float g_score[NN];
__device__ int   g_noo[NN];
__device__ float g_out[BGR*HD];
__device__ float g_pn[2];

// ---------------- helpers ----------------
__device__ __forceinline__ uint32_t smem_u32(const void* p) {
    uint32_t a;
    asm("{ .reg .u64 t; cvta.to.shared.u64 t, %1; cvt.u32.u64 %0, t; }" : "=r"(a) : "l"(p));
    return a;
}
#define SWZ128(o) ((o) ^ (((o) >> 3) & 0x70))

__device__ __forceinline__ void ldm4(uint32_t* r, uint32_t addr) {
    asm volatile("ldmatrix.sync.aligned.m8n8.x4.shared.b16 {%0,%1,%2,%3}, [%4];"
        : "=r"(r[0]), "=r"(r[1]), "=r"(r[2]), "=r"(r[3]) : "r"(addr));
}
__device__ __forceinline__ void mma16816(float* d, const uint32_t* a, const uint32_t* b) {
    asm volatile("mma.sync.aligned.m16n8k16.row.col.f32.bf16.bf16.f32 "
        "{%0,%1,%2,%3}, {%4,%5,%6,%7}, {%8,%9}, {%0,%1,%2,%3};"
        : "+f"(d[0]), "+f"(d[1]), "+f"(d[2]), "+f"(d[3])
        : "r"(a[0]), "r"(a[1]), "r"(a[2]), "r"(a[3]), "r"(b[0]), "r"(b[1]));
}
__device__ __forceinline__ void cpa16(uint32_t d, const void* s) {
    asm volatile("cp.async.cg.shared.global [%0], [%1], 16;" :: "r"(d), "l"(s));
}
#define CP_COMMIT() asm volatile("cp.async.commit_group;" ::: "memory")
#define CP_WAIT1()  asm volatile("cp.async.wait_group 1;" ::: "memory")
#define CP_WAIT0()  asm volatile("cp.async.wait_group 0;" ::: "memory")

// C[M,256] = (Ah+Al)[M,256] @ Wt^T, 3-term bf16 split, double-buffered cp.async.
#define TCH 16384                 // one 128x64 bf16 tile
#define TC_SMEM (8*TCH + 1024)
__global__ __launch_bounds__(512)
void k_gemm_mma(const __nv_bfloat16* __restrict__ Ah, const __nv_bfloat16* __restrict__ Al,
                const __nv_bfloat16* __restrict__ Bth, const __nv_bfloat16* __restrict__ Btl,
                float* __restrict__ C) {
    extern __shared__ char dyn[];
    char* base = (char*)((((uintptr_t)dyn) + 1023) & ~(uintptr_t)1023);
    uint32_t sbase = smem_u32(base);
    int tid = threadIdx.x;
    int wid = tid >> 5, lane = tid & 31;
    int wm = wid & 3, wn = wid >> 2;
    int bn = blockIdx.x, bm = blockIdx.y;
    int row0 = bm * 128, n0g = bn * 128;

    float acc[2][4][4];
#pragma unroll
    for (int mt = 0; mt < 2; mt++)
#pragma unroll
        for (int nt = 0; nt < 4; nt++)
#pragma unroll
            for (int r = 0; r < 4; r++) acc[mt][nt][r] = 0.f;

    // stage chunk into buffer buf via cp.async
    auto stage = [&](int buf, int chunk) {
        uint32_t b = sbase + buf*4*TCH;
        int col0 = chunk * 64;
#pragma unroll
        for (int t = 0; t < 2; t++) {
            int f = tid + t * 512;
            int r = f >> 3, c8 = (f & 7) * 8;
            uint32_t so = SWZ128((uint32_t)(r * 128 + c8 * 2));
            cpa16(b + 0*TCH + so, &Ah [(size_t)(row0 + r)*HD + col0 + c8]);
            cpa16(b + 1*TCH + so, &Al [(size_t)(row0 + r)*HD + col0 + c8]);
            cpa16(b + 2*TCH + so, &Bth[(size_t)(n0g  + r)*HD + col0 + c8]);
            cpa16(b + 3*TCH + so, &Btl[(size_t)(n0g  + r)*HD + col0 + c8]);
        }
    };

    stage(0, 0); CP_COMMIT();
    for (int chunk = 0; chunk < 4; chunk++) {
        if (chunk < 3) { stage((chunk+1)&1, chunk+1); CP_COMMIT(); CP_WAIT1(); }
        else CP_WAIT0();
        __syncthreads();
        uint32_t bb = sbase + (chunk&1)*4*TCH;
#pragma unroll
        for (int ks = 0; ks < 4; ks++) {
            int k0 = ks * 16;
            uint32_t a_h[2][4], a_l[2][4], b_h[2][4], b_l[2][4];
#pragma unroll
            for (int mt = 0; mt < 2; mt++) {
                int arow = wm*32 + mt*16 + (lane & 7) + (lane & 8);
                int acol = k0 + (((lane >> 4) & 1) << 3);
                uint32_t so = SWZ128((uint32_t)(arow * 128 + acol * 2));
                ldm4(a_h[mt], bb + 0*TCH + so);
                ldm4(a_l[mt], bb + 1*TCH + so);
            }
#pragma unroll
            for (int np = 0; np < 2; np++) {
                int brow = wn*32 + np*16 + (lane & 7) + (((lane >> 4) & 1) << 3);
                int bcol = k0 + (lane & 8);
                uint32_t so = SWZ128((uint32_t)(brow * 128 + bcol * 2));
                ldm4(b_h[np], bb + 2*TCH + so);
                ldm4(b_l[np], bb + 3*TCH + so);
            }
#pragma unroll
            for (int mt = 0; mt < 2; mt++)
#pragma unroll
                for (int nt = 0; nt < 4; nt++) {
                    const uint32_t* bh = &b_h[nt >> 1][(nt & 1) * 2];
                    const uint32_t* bl = &b_l[nt >> 1][(nt & 1) * 2];
                    mma16816(acc[mt][nt], a_h[mt], bh);
                    mma16816(acc[mt][nt], a_h[mt], bl);
                    mma16816(acc[mt][nt], a_l[mt], bh);
                }
        }
        __syncthreads();
    }

    int g = lane >> 2, i2 = (lane & 3) * 2;
#pragma unroll
    for (int mt = 0; mt < 2; mt++)
#pragma unroll
        for (int nt = 0; nt < 4; nt++) {
            int r = row0 + wm*32 + mt*16 + g;
            int c = n0g + wn*32 + nt*8 + i2;
            float2 v0 = {acc[mt][nt][0], acc[mt][nt][1]};
            float2 v1 = {acc[mt][nt][2], acc[mt][nt][3]};
            *(float2*)&C[(size_t)r*HD + c] = v0;
            *(float2*)&C[(size_t)(r+8)*HD + c] = v1;
        }
}

// ---------------- other kernels ----------------

// token embed + masked mean -> bf16 hi/lo. grid=NN, block=256
__global__ void k_st(const int* __restrict__ tok, const float* __restrict__ emb,
                     __nv_bfloat16* __restrict__ xh, __nv_bfloat16* __restrict__ xl) {
    int n = blockIdx.x, c = threadIdx.x;
    float acc = 0.f; int cnt = 0;
#pragma unroll
    for (int l = 0; l < LTOK; l++) {
        int t = tok[n*LTOK + l];
        if (t != 0) { acc += emb[(size_t)t*HD + c]; cnt++; }
    }
    float m = acc / fmaxf((float)cnt, 1.f);
    __nv_bfloat16 hi = __float2bfloat16(m);
    xh[(size_t)n*HD + c] = hi;
    xl[(size_t)n*HD + c] = __float2bfloat16(m - __bfloat162float(hi));
}

// transpose + bf16-split both weight matrices. grid (8,8,2), block (32,32)
__global__ void k_convW(const float* __restrict__ W0, const float* __restrict__ W1,
                        __nv_bfloat16* __restrict__ wth, __nv_bfloat16* __restrict__ wtl) {
    __shared__ float t[32][33];
    const float* W = blockIdx.z ? W1 : W0;
    int k0 = blockIdx.x*32, n0 = blockIdx.y*32;
    t[threadIdx.y][threadIdx.x] = W[(size_t)(k0+threadIdx.y)*HD + n0+threadIdx.x];
    __syncthreads();
    float v = t[threadIdx.x][threadIdx.y];
    __nv_bfloat16 hi = __float2bfloat16(v);
    size_t o = (size_t)blockIdx.z*HD*HD + (size_t)(n0+threadIdx.y)*HD + k0+threadIdx.x;
    wth[o] = hi;
    wtl[o] = __float2bfloat16(v - __bfloat162float(hi));
}

__global__ void k_setup(const float* __restrict__ ea, float* __restrict__ w,
                        float* __restrict__ deg, int* __restrict__ cnt,
                        int* __restrict__ noo, int E, int n) {
    int e = blockIdx.x*blockDim.x + threadIdx.x;
    if (e < E) w[e] = 0.5f*(ea[2*e] + ea[2*e+1]);
    if (e < n) { deg[e] = 1.f; cnt[e] = 0; noo[e] = -1; }
}

__global__ void k_degcnt(const int* __restrict__ dst, const float* __restrict__ w,
                         float* deg, int* cnt, int E) {
    int e = blockIdx.x*blockDim.x + threadIdx.x;
    if (e >= E) return;
    float we = w[e];
    if (we != 0.f) {
        atomicAdd(&deg[dst[e]], we);
        atomicAdd(&cnt[dst[e]], 1);
    }
}

__global__ void k_scan1(const int* __restrict__ cnt, int* __restrict__ off,
                        int* __restrict__ bsum) {
    __shared__ int warpsum[32];
    int tid = threadIdx.x;
    int gid = blockIdx.x*1024 + tid;
    int lane = tid & 31, wid = tid >> 5;
    int v = cnt[gid];
    int s = v;
#pragma unroll
    for (int d = 1; d < 32; d <<= 1) {
        int t = __shfl_up_sync(~0u, s, d);
        if (lane >= d) s += t;
    }
    if (lane == 31) warpsum[wid] = s;
    __syncthreads();
    if (wid == 0) {
        int w = warpsum[lane];
#pragma unroll
        for (int d = 1; d < 32; d <<= 1) {
            int t = __shfl_up_sync(~0u, w, d);
            if (lane >= d) w += t;
        }
        warpsum[lane] = w;
    }
    __syncthreads();
    int excl = s - v + (wid ? warpsum[wid-1] : 0);
    off[gid] = excl;
    if (tid == 1023) bsum[blockIdx.x] = excl + v;
}

__global__ void k_scan2(int* __restrict__ off, int* __restrict__ cur,
                        const int* __restrict__ bsum, int n) {
    __shared__ int sh[33];
    int tid = threadIdx.x;
    if (tid < 32) {
        int nb = gridDim.x;
        int v = (tid < nb) ? bsum[tid] : 0;
#pragma unroll
        for (int d = 1; d < 32; d <<= 1) {
            int t = __shfl_up_sync(~0u, v, d);
            if (tid >= d) v += t;
        }
        sh[tid+1] = v;
        if (tid == 0) sh[0] = 0;
    }
    __syncthreads();
    int add = sh[blockIdx.x];
    int gid = blockIdx.x*1024 + tid;
    int o = off[gid] + add;
    off[gid] = o;
    cur[gid] = o;
    if (gid == n - 1) off[n] = sh[gridDim.x];
}

__global__ void k_scatter(const int* __restrict__ src, const int* __restrict__ dst,
                          const float* __restrict__ w, const float* __restrict__ deg,
                          int* cur, int* __restrict__ csr_src,
                          float* __restrict__ csr_nrm, int E) {
    int e = blockIdx.x*blockDim.x + threadIdx.x;
    if (e >= E) return;
    float we = w[e];
    if (we == 0.f) return;
    int s = src[e], d = dst[e];
    int p = atomicAdd(&cur[d], 1);
    csr_src[p] = s;
    csr_nrm[p] = rsqrtf(deg[s]) * we * rsqrtf(deg[d]);
}

// agg + self + bias + relu, fused top-k score. grid=n, block=256
__global__ void k_agg_score(const float* __restrict__ h, const int* __restrict__ csr_src,
                            const float* __restrict__ csr_nrm, const int* __restrict__ off,
                            const float* __restrict__ deg, const float* __restrict__ bias,
                            const float* __restrict__ p, const float* __restrict__ pn,
                            int pidx, float* __restrict__ xout, float* __restrict__ score) {
    __shared__ int   ss[256];
    __shared__ float sn[256];
    __shared__ float red[256];
    int v = blockIdx.x, c = threadIdx.x;
    int s0 = off[v], s1 = off[v+1];
    float acc = 0.f;
    for (int base = s0; base < s1; base += 256) {
        int m = min(256, s1 - base);
        if (c < m) { ss[c] = csr_src[base + c]; sn[c] = csr_nrm[base + c]; }
        __syncthreads();
        int k = 0;
        for (; k + 4 <= m; k += 4) {
            float a0 = h[(size_t)ss[k+0]*HD + c];
            float a1 = h[(size_t)ss[k+1]*HD + c];
            float a2 = h[(size_t)ss[k+2]*HD + c];
            float a3 = h[(size_t)ss[k+3]*HD + c];
            acc += a0*sn[k+0] + a1*sn[k+1] + a2*sn[k+2] + a3*sn[k+3];
        }
        for (; k < m; k++) acc += h[(size_t)ss[k]*HD + c] * sn[k];
        __syncthreads();
    }
    float r = acc + h[(size_t)v*HD + c] / deg[v] + bias[c];
    r = fmaxf(r, 0.f);
    xout[(size_t)v*HD + c] = r;
    red[c] = r * p[c];
    __syncthreads();
    for (int s = 128; s > 0; s >>= 1) { if (c < s) red[c] += red[c+s]; __syncthreads(); }
    if (c == 0) score[v] = red[0] * pn[pidx];
}

__global__ void k_pnorm(const float* __restrict__ p0, const float* __restrict__ p1,
                        float* __restrict__ pn) {
    __shared__ float red[256];
    int tid = threadIdx.x;
    float v0 = p0[tid], v1 = p1[tid];
    red[tid] = v0*v0; __syncthreads();
    for (int s = 128; s > 0; s >>= 1) { if (tid < s) red[tid] += red[tid+s]; __syncthreads(); }
    if (tid == 0) pn[0] = 1.f / sqrtf(red[0]);
    __syncthreads();
    red[tid] = v1*v1; __syncthreads();
    for (int s = 128; s > 0; s >>= 1) { if (tid < s) red[tid] += red[tid+s]; __syncthreads(); }
    if (tid == 0) pn[1] = 1.f / sqrtf(red[0]);
}

__device__ __forceinline__ void bf16split4(float4 v, __nv_bfloat16* ph, __nv_bfloat16* pl) {
    float a[4] = {v.x, v.y, v.z, v.w};
#pragma unroll
    for (int i = 0; i < 4; i++) {
        __nv_bfloat16 h = __float2bfloat16(a[i]);
        ph[i] = h;
        pl[i] = __float2bfloat16(a[i] - __bfloat162float(h));
    }
}

// ---- fused pool 1: topk(512->256) + gather/gate + attpool. grid=BGR, block=512
__global__ __launch_bounds__(512)
void k_pool1(const float* __restrict__ score, const float* __restrict__ x,
             const float* __restrict__ wg, const float* __restrict__ bg,
             int* __restrict__ noo, float* __restrict__ x1,
             __nv_bfloat16* __restrict__ xh, __nv_bfloat16* __restrict__ xl,
             float* __restrict__ out) {
    __shared__ float s[NPG];
    __shared__ int   id[NPG];
    __shared__ float gates[KP1];
    __shared__ float wgs[HD];
    __shared__ float red[512];
    int tid = threadIdx.x, g = blockIdx.x;
    int lane = tid & 31, wid = tid >> 5;

    s[tid] = score[g*NPG + tid];
    id[tid] = tid;
    if (tid < HD) wgs[tid] = wg[tid];
    __syncthreads();
    // bitonic sort desc (score desc, idx asc tie-break)
    for (int k = 2; k <= NPG; k <<= 1) {
        for (int j = k >> 1; j > 0; j >>= 1) {
            int ixj = tid ^ j;
            if (ixj > tid) {
                bool desc = ((tid & k) == 0);
                float sa = s[tid], sb = s[ixj];
                int ia = id[tid], ib = id[ixj];
                bool a_first = (sa > sb) || (sa == sb && ia < ib);
                bool swp = desc ? !a_first : a_first;
                if (swp) { s[tid] = sb; s[ixj] = sa; id[tid] = ib; id[ixj] = ia; }
            }
            __syncthreads();
        }
    }
    // warp-per-row gather + gate dot
    float bgv = bg[0];
    for (int j = wid; j < KP1; j += 16) {
        int old = g*NPG + id[j];
        float gv = tanhf(s[j]);
        const float* xr = x + (size_t)old*HD;
        float4 v0 = *(const float4*)&xr[lane*4];
        float4 v1 = *(const float4*)&xr[128 + lane*4];
        v0.x *= gv; v0.y *= gv; v0.z *= gv; v0.w *= gv;
        v1.x *= gv; v1.y *= gv; v1.z *= gv; v1.w *= gv;
        int nrow = g*KP1 + j;
        float* x1r = x1 + (size_t)nrow*HD;
        *(float4*)&x1r[lane*4] = v0;
        *(float4*)&x1r[128 + lane*4] = v1;
        __nv_bfloat16 h4[4], l4[4];
        bf16split4(v0, h4, l4);
        *(uint2*)&xh[(size_t)nrow*HD + lane*4] = *(uint2*)h4;
        *(uint2*)&xl[(size_t)nrow*HD + lane*4] = *(uint2*)l4;
        bf16split4(v1, h4, l4);
        *(uint2*)&xh[(size_t)nrow*HD + 128 + lane*4] = *(uint2*)h4;
        *(uint2*)&xl[(size_t)nrow*HD + 128 + lane*4] = *(uint2*)l4;
        float d = v0.x*wgs[lane*4+0] + v0.y*wgs[lane*4+1]
                + v0.z*wgs[lane*4+2] + v0.w*wgs[lane*4+3]
                + v1.x*wgs[128+lane*4+0] + v1.y*wgs[128+lane*4+1]
                + v1.z*wgs[128+lane*4+2] + v1.w*wgs[128+lane*4+3];
#pragma unroll
        for (int o = 16; o > 0; o >>= 1) d += __shfl_down_sync(~0u, d, o);
        if (lane == 0) { gates[j] = d + bgv; noo[old] = nrow; }
    }
    __syncthreads();
    // softmax over gates[0..KP1)
    if (tid < KP1) red[tid] = gates[tid];
    __syncthreads();
    for (int st = KP1/2; st > 0; st >>= 1) { if (tid < st) red[tid] = fmaxf(red[tid], red[tid+st]); __syncthreads(); }
    float m = red[0]; __syncthreads();
    float e = (tid < KP1) ? expf(gates[tid] - m) : 0.f;
    if (tid < KP1) red[tid] = e;
    __syncthreads();
    for (int st = KP1/2; st > 0; st >>= 1) { if (tid < st) red[tid] += red[tid+st]; __syncthreads(); }
    float sum = red[0]; __syncthreads();
    if (tid < KP1) gates[tid] = e / sum;
    __syncthreads();
    // weighted sum (2-way split over rows)
    int c = tid & (HD-1), half = tid >> 8;
    float acc = 0.f;
    const float* xb = x1 + (size_t)g*KP1*HD;
    for (int j = half*(KP1/2); j < (half+1)*(KP1/2); j++)
        acc += gates[j] * xb[(size_t)j*HD + c];
    red[tid] = acc;
    __syncthreads();
    if (tid < HD) out[g*HD + tid] = red[tid] + red[tid + HD];
}

// ---- fused pool 2: topk(256->128) + gather/gate + attpool (rows in smem, accum)
#define P2_SMEM (KP2*HD*4)
__global__ __launch_bounds__(256)
void k_pool2(const float* __restrict__ score, const float* __restrict__ x,
             const float* __restrict__ wg, const float* __restrict__ bg,
             float* __restrict__ out) {
    extern __shared__ float rows[];   // [KP2][HD]
    __shared__ float s[KP1];
    __shared__ int   id[KP1];
    __shared__ float gates[KP2];
    __shared__ float wgs[HD];
    __shared__ float red[256];
    int tid = threadIdx.x, g = blockIdx.x;
    int lane = tid & 31, wid = tid >> 5;

    s[tid] = score[g*KP1 + tid];
    id[tid] = tid;
    wgs[tid] = wg[tid];
    __syncthreads();
    for (int k = 2; k <= KP1; k <<= 1) {
        for (int j = k >> 1; j > 0; j >>= 1) {
            int ixj = tid ^ j;
            if (ixj > tid) {
                bool desc = ((tid & k) == 0);
                float sa = s[tid], sb = s[ixj];
                int ia = id[tid], ib = id[ixj];
                bool a_first = (sa > sb) || (sa == sb && ia < ib);
                bool swp = desc ? !a_first : a_first;
                if (swp) { s[tid] = sb; s[ixj] = sa; id[tid] = ib; id[ixj] = ia; }
            }
            __syncthreads();
        }
    }
    float bgv = bg[0];
    for (int j = wid; j < KP2; j += 8) {
        int old = g*KP1 + id[j];
        float gv = tanhf(s[j]);
        const float* xr = x + (size_t)old*HD;
        float4 v0 = *(const float4*)&xr[lane*4];
        float4 v1 = *(const float4*)&xr[128 + lane*4];
        v0.x *= gv; v0.y *= gv; v0.z *= gv; v0.w *= gv;
        v1.x *= gv; v1.y *= gv; v1.z *= gv; v1.w *= gv;
        *(float4*)&rows[j*HD + lane*4] = v0;
        *(float4*)&rows[j*HD + 128 + lane*4] = v1;
        float d = v0.x*wgs[lane*4+0] + v0.y*wgs[lane*4+1]
                + v0.z*wgs[lane*4+2] + v0.w*wgs[lane*4+3]
                + v1.x*wgs[128+lane*4+0] + v1.y*wgs[128+lane*4+1]
                + v1.z*wgs[128+lane*4+2] + v1.w*wgs[128+lane*4+3];
#pragma unroll
        for (int o = 16; o > 0; o >>= 1) d += __shfl_down_sync(~0u, d, o);
        if (lane == 0) gates[j] = d + bgv;
    }
    __syncthreads();
    // softmax over gates[0..KP2)
    if (tid < KP2) red[tid] = gates[tid];
    __syncthreads();
    for (int st = KP2/2; st > 0; st >>= 1) { if (tid < st) red[tid] = fmaxf(red[tid], red[tid+st]); __syncthreads(); }
    float m = red[0]; __syncthreads();
    float e = (tid < KP2) ? expf(gates[tid] - m) : 0.f;
    if (tid < KP2) red[tid] = e;
    __syncthreads();
    for (int st = KP2/2; st > 0; st >>= 1) { if (tid < st) red[tid] += red[tid+st]; __syncthreads(); }
    float sum = red[0]; __syncthreads();
    if (tid < KP2) gates[tid] = e / sum;
    __syncthreads();
    // weighted sum from smem rows
    float acc = 0.f;
#pragma unroll 4
    for (int j = 0; j < KP2; j++)
        acc += gates[j] * rows[j*HD + tid];
    out[g*HD + tid] += acc;
}

// edge remap + layer-2 deg/cnt init fused
__global__ void k_remap(const int* __restrict__ src, const int* __restrict__ dst,
                        const float* __restrict__ w, const int* __restrict__ noo,
                        int* __restrict__ src1, int* __restrict__ dst1,
                        float* __restrict__ w1, float* __restrict__ deg,
                        int* __restrict__ cnt, int E, int n) {
    int e = blockIdx.x*blockDim.x + threadIdx.x;
    if (e < E) {
        int ns = noo[src[e]], nd = noo[dst[e]];
        bool keep = (ns >= 0) && (nd >= 0);
        src1[e] = keep ? ns : 0;
        dst1[e] = keep ? nd : 0;
        w1[e]   = keep ? w[e] : 0.f;
    }
    if (e < n) { deg[e] = 1.f; cnt[e] = 0; }
}

// projection head + L2 norm + output write. grid = B, block = 128
__global__ void k_proj(const float* __restrict__ out, const float* __restrict__ Wp1,
                       const float* __restrict__ bp1, const float* __restrict__ Wp2,
                       const float* __restrict__ bp2, float* logits_dst, float* out_dst) {
    __shared__ float o[HD];
    __shared__ float hh[PDIM];
    __shared__ float red[PDIM];
    int g = blockIdx.x, tid = threadIdx.x;
    o[tid] = out[g*HD + tid];
    o[tid + 128] = out[g*HD + 128 + tid];
    __syncthreads();
    float s = bp1[tid];
    for (int i = 0; i < HD; i++) s += o[i] * Wp1[i*PDIM + tid];
    hh[tid] = fmaxf(s, 0.f);
    __syncthreads();
    float t = bp2[tid];
    for (int i = 0; i < PDIM; i++) t += hh[i] * Wp2[i*PDIM + tid];
    red[tid] = t*t; __syncthreads();
    for (int st = 64; st > 0; st >>= 1) { if (tid < st) red[tid] += red[tid+st]; __syncthreads(); }
    float nrm = fmaxf(sqrtf(red[0]), 1e-12f);
    if (logits_dst) logits_dst[g*PDIM + tid] = t / nrm;
    if (out_dst) {
        out_dst[g*HD + tid] = o[tid];
        out_dst[g*HD + 128 + tid] = o[tid + 128];
    }
}

// ---------------- host launch ----------------
extern "C" void kernel_launch(void* const* d_in, const int* in_sizes, int n_in,
                              void* d_out, int out_size) {
    const int*   tokens    = (const int*)d_in[0];
    const int*   src       = (const int*)d_in[1];
    const int*   dst       = (const int*)d_in[2];
    const float* edge_attr = (const float*)d_in[3];
    const float* emb       = (const float*)d_in[4];
    const float* W0        = (const float*)d_in[5];
    const float* b0        = (const float*)d_in[6];
    const float* W1        = (const float*)d_in[7];
    const float* b1        = (const float*)d_in[8];
    const float* p0        = (const float*)d_in[9];
    const float* p1        = (const float*)d_in[10];
    const float* wg        = (const float*)d_in[11];
    const float* bg        = (const float*)d_in[12];
    const float* Wp1       = (const float*)d_in[13];
    const float* bp1       = (const float*)d_in[14];
    const float* Wp2       = (const float*)d_in[15];
    const float* bp2       = (const float*)d_in[16];

    float *x,*h,*x1,*w,*w1,*deg,*csr_nrm,*score,*outb,*pn;
    __nv_bfloat16 *xh,*xl,*wth,*wtl;
    int *src1,*dst1,*cnt,*off,*cur,*bsum,*csr_src,*noo;
    cudaGetSymbolAddress((void**)&x, g_x);
    cudaGetSymbolAddress((void**)&h, g_h);
    cudaGetSymbolAddress((void**)&x1, g_x1);
    cudaGetSymbolAddress((void**)&xh, g_xh);
    cudaGetSymbolAddress((void**)&xl, g_xl);
    cudaGetSymbolAddress((void**)&wth, g_wth);
    cudaGetSymbolAddress((void**)&wtl, g_wtl);
    cudaGetSymbolAddress((void**)&w, g_w);
    cudaGetSymbolAddress((void**)&w1, g_w1);
    cudaGetSymbolAddress((void**)&src1, g_src1);
    cudaGetSymbolAddress((void**)&dst1, g_dst1);
    cudaGetSymbolAddress((void**)&deg, g_deg);
    cudaGetSymbolAddress((void**)&cnt, g_cnt);
    cudaGetSymbolAddress((void**)&off, g_off);
    cudaGetSymbolAddress((void**)&cur, g_cur);
    cudaGetSymbolAddress((void**)&bsum, g_bsum);
    cudaGetSymbolAddress((void**)&csr_src, g_csr_src);
    cudaGetSymbolAddress((void**)&csr_nrm, g_csr_nrm);
    cudaGetSymbolAddress((void**)&score, g_score);
    cudaGetSymbolAddress((void**)&noo, g_noo);
    cudaGetSymbolAddress((void**)&outb, g_out);
    cudaGetSymbolAddress((void**)&pn, g_pn);

    static cudaStream_t sB;
    static cudaEvent_t e0, eW, eCSR, eT1, eCSR2;
    static int inited = 0;
    if (!inited) {
        cudaFuncSetAttribute(k_gemm_mma, cudaFuncAttributeMaxDynamicSharedMemorySize, TC_SMEM);
        cudaFuncSetAttribute(k_pool2, cudaFuncAttributeMaxDynamicSharedMemorySize, P2_SMEM);
        cudaStreamCreateWithFlags(&sB, cudaStreamNonBlocking);
        cudaEventCreateWithFlags(&e0,    cudaEventDisableTiming);
        cudaEventCreateWithFlags(&eW,    cudaEventDisableTiming);
        cudaEventCreateWithFlags(&eCSR,  cudaEventDisableTiming);
        cudaEventCreateWithFlags(&eT1,   cudaEventDisableTiming);
        cudaEventCreateWithFlags(&eCSR2, cudaEventDisableTiming);
        inited = 1;
    }

    // fork aux stream
    cudaEventRecord(e0, 0);
    cudaStreamWaitEvent(sB, e0, 0);

    // ---- aux stream: pnorm + weight conversion + edge/CSR chain (layer 1) ----
    k_pnorm<<<1, 256, 0, sB>>>(p0, p1, pn);
    k_convW<<<dim3(8,8,2), dim3(32,32), 0, sB>>>(W0, W1, wth, wtl);
    cudaEventRecord(eW, sB);
    k_setup<<<EE/256, 256, 0, sB>>>(edge_attr, w, deg, cnt, noo, EE, NN);
    k_degcnt<<<EE/256, 256, 0, sB>>>(dst, w, deg, cnt, EE);
    k_scan1<<<NN/1024, 1024, 0, sB>>>(cnt, off, bsum);
    k_scan2<<<NN/1024, 1024, 0, sB>>>(off, cur, bsum, NN);
    k_scatter<<<EE/256, 256, 0, sB>>>(src, dst, w, deg, cur, csr_src, csr_nrm, EE);
    cudaEventRecord(eCSR, sB);

    // ---- main stream: token chain ----
    k_st<<<NN, 256>>>(tokens, emb, xh, xl);
    cudaStreamWaitEvent(0, eW, 0);
    k_gemm_mma<<<dim3(2, NN/128), 512, TC_SMEM>>>(xh, xl, wth, wtl, h);
    cudaStreamWaitEvent(0, eCSR, 0);
    k_agg_score<<<NN, 256>>>(h, csr_src, csr_nrm, off, deg, b0, p0, pn, 0, x, score);
    // fused pool 1 (topk + gather/gate/bf16 + attpool -> outb)
    k_pool1<<<BGR, 512>>>(score, x, wg, bg, noo, x1, xh, xl, outb);
    cudaEventRecord(eT1, 0);

    // ---- aux stream: layer-2 CSR rebuild (needs noo from pool1) ----
    cudaStreamWaitEvent(sB, eT1, 0);
    k_remap<<<EE/256, 256, 0, sB>>>(src, dst, w, noo, src1, dst1, w1, deg, cnt, EE, N2);
    k_degcnt<<<EE/256, 256, 0, sB>>>(dst1, w1, deg, cnt, EE);
    k_scan1<<<N2/1024, 1024, 0, sB>>>(cnt, off, bsum);
    k_scan2<<<N2/1024, 1024, 0, sB>>>(off, cur, bsum, N2);
    k_scatter<<<EE/256, 256, 0, sB>>>(src1, dst1, w1, deg, cur, csr_src, csr_nrm, EE);
    cudaEventRecord(eCSR2, sB);

    // ---- main stream: gemm2 (overlaps CSR rebuild) ----
    k_gemm_mma<<<dim3(2, N2/128), 512, TC_SMEM>>>(xh, xl, wth + HD*HD, wtl + HD*HD, h);
    cudaStreamWaitEvent(0, eCSR2, 0);
    k_agg_score<<<N2, 256>>>(h, csr_src, csr_nrm, off, deg, b1, p1, pn, 1, x, score);
    // fused pool 2 (accumulates into outb)
    k_pool2<<<BGR, 256, P2_SMEM>>>(score, x, wg, bg, outb);

    // projection head + outputs
    float* logits_dst = (float*)d_out;
    float* out_dst = nullptr;
    if (out_size >= BGR*PDIM + BGR*HD) {
        out_dst = (float*)d_out + BGR*PDIM;
    } else if (out_size == BGR*HD) {
        logits_dst = nullptr;
        out_dst = (float*)d_out;
    }
    k_proj<<<BGR, 128>>>(outb, Wp1, bp1, Wp2, bp2, logits_dst, out_dst);
}